// round 15
// baseline (speedup 1.0000x reference)
#include <cuda_runtime.h>
#include <cuda_fp16.h>
#include <stdint.h>
#include <math.h>

// Problem constants
#define BATCH 2
#define SEQ 2048
#define DMODEL 1024
#define NHEADS 16
#define DHEAD 64
#define DFF 4096
#define NTOK (BATCH * SEQ)   // 4096

// ---------------------------------------------------------------------------
// Scratch (device globals; allocation is forbidden)
// ---------------------------------------------------------------------------
__device__ __half g_h1[NTOK * DMODEL];
__device__ __half g_q [NTOK * DMODEL];
__device__ __half g_k [NTOK * DMODEL];
__device__ __half g_v [NTOK * DMODEL];
__device__ __half g_o [NTOK * DMODEL];
__device__ float  g_x2[NTOK * DMODEL];
__device__ __half g_a [NTOK * DFF];
// fp16 weights
__device__ __half g_wq[DMODEL * DMODEL];
__device__ __half g_wk[DMODEL * DMODEL];
__device__ __half g_wv[DMODEL * DMODEL];
__device__ __half g_wo[DMODEL * DMODEL];
__device__ __half g_w1[DFF * DMODEL];
__device__ __half g_w2[DMODEL * DFF];
__device__ __half g_w3[DFF * DMODEL];

// ---------------------------------------------------------------------------
// mma.sync helpers
// ---------------------------------------------------------------------------
__device__ __forceinline__ void mma_f16(float* c, const unsigned int* a, const unsigned int* b) {
    asm volatile(
        "mma.sync.aligned.m16n8k16.row.col.f32.f16.f16.f32 "
        "{%0,%1,%2,%3}, {%4,%5,%6,%7}, {%8,%9}, {%0,%1,%2,%3};"
        : "+f"(c[0]), "+f"(c[1]), "+f"(c[2]), "+f"(c[3])
        : "r"(a[0]), "r"(a[1]), "r"(a[2]), "r"(a[3]), "r"(b[0]), "r"(b[1]));
}
__device__ __forceinline__ void ldsm4h(unsigned int* r, const __half* p) {
    unsigned int addr = (unsigned int)__cvta_generic_to_shared(p);
    asm volatile("ldmatrix.sync.aligned.m8n8.x4.shared.b16 {%0,%1,%2,%3}, [%4];"
                 : "=r"(r[0]), "=r"(r[1]), "=r"(r[2]), "=r"(r[3]) : "r"(addr));
}
__device__ __forceinline__ void ldsm4ht(unsigned int* r, const __half* p) {
    unsigned int addr = (unsigned int)__cvta_generic_to_shared(p);
    asm volatile("ldmatrix.sync.aligned.m8n8.x4.trans.shared.b16 {%0,%1,%2,%3}, [%4];"
                 : "=r"(r[0]), "=r"(r[1]), "=r"(r[2]), "=r"(r[3]) : "r"(addr));
}
__device__ __forceinline__ float ex2f(float x) {
    float y;
    asm("ex2.approx.ftz.f32 %0, %1;" : "=f"(y) : "f"(x));
    return y;
}

// SW128 swizzled pointer within a [rows x 128 bytes] tile. halfcol multiple of 8.
__device__ __forceinline__ const __half* swp(const __half* base, int row, int halfcol) {
    unsigned int off = (unsigned int)(row * 128) +
        (((unsigned int)(halfcol * 2)) ^ (((unsigned int)row & 7u) * 16u));
    return (const __half*)((const char*)base + off);
}

// convert helper: 16 floats -> 16 halfs at unit index `off`
__device__ __forceinline__ void cvt16(const float* __restrict__ src,
                                      __half* __restrict__ dst, int off) {
    float4 v0 = *(const float4*)(src + (size_t)off * 16);
    float4 v1 = *(const float4*)(src + (size_t)off * 16 + 4);
    float4 v2 = *(const float4*)(src + (size_t)off * 16 + 8);
    float4 v3 = *(const float4*)(src + (size_t)off * 16 + 12);
    __half2 h[8];
    h[0] = __floats2half2_rn(v0.x, v0.y);
    h[1] = __floats2half2_rn(v0.z, v0.w);
    h[2] = __floats2half2_rn(v1.x, v1.y);
    h[3] = __floats2half2_rn(v1.z, v1.w);
    h[4] = __floats2half2_rn(v2.x, v2.y);
    h[5] = __floats2half2_rn(v2.z, v2.w);
    h[6] = __floats2half2_rn(v3.x, v3.y);
    h[7] = __floats2half2_rn(v3.z, v3.w);
    *(uint4*)(dst + (size_t)off * 16)     = ((uint4*)h)[0];
    *(uint4*)(dst + (size_t)off * 16 + 8) = ((uint4*)h)[1];
}

// ---------------------------------------------------------------------------
// Prelude: rmsnorm1 + d_model-square weight converts (Wq,Wk,Wv,Wo).
// FF weights (W1,W2,W3) are converted inside the QKV GEMM launch (z==3).
// ---------------------------------------------------------------------------
#define NDD16 (DMODEL * DMODEL / 16)   // 65536
#define NFF16 (DFF * DMODEL / 16)      // 262144
#define NDDCVT (4 * NDD16 / 256)       // 1024 blocks

__global__ __launch_bounds__(256) void prelude_kernel(
    const float* __restrict__ x, const float* __restrict__ g1,
    __half* __restrict__ h1,
    const float* __restrict__ s0, const float* __restrict__ s1,
    const float* __restrict__ s2, const float* __restrict__ s3,
    __half* __restrict__ d0, __half* __restrict__ d1,
    __half* __restrict__ d2, __half* __restrict__ d3)
{
    const int tid = threadIdx.x;

    if (blockIdx.x < NTOK) {
        const int row = blockIdx.x;
        const float* xr = x + (size_t)row * DMODEL;

        float4 v = *(const float4*)(xr + tid * 4);
        float ss = v.x * v.x + v.y * v.y + v.z * v.z + v.w * v.w;

        #pragma unroll
        for (int off = 16; off; off >>= 1)
            ss += __shfl_xor_sync(0xffffffffu, ss, off);

        __shared__ float red[8];
        const int lane = tid & 31, warp = tid >> 5;
        if (lane == 0) red[warp] = ss;
        __syncthreads();
        if (warp == 0) {
            float t = (lane < 8) ? red[lane] : 0.0f;
            #pragma unroll
            for (int off = 4; off; off >>= 1)
                t += __shfl_xor_sync(0xffffffffu, t, off);
            if (lane == 0) red[0] = t;
        }
        __syncthreads();

        const float inv = rsqrtf(red[0] * (1.0f / DMODEL) + 1e-5f);
        float4 gv = *(const float4*)(g1 + tid * 4);
        __half2 h0 = __floats2half2_rn(v.x * inv * gv.x, v.y * inv * gv.y);
        __half2 hh = __floats2half2_rn(v.z * inv * gv.z, v.w * inv * gv.w);
        __half* yp = h1 + (size_t)row * DMODEL + tid * 4;
        *(__half2*)(yp)     = h0;
        *(__half2*)(yp + 2) = hh;
    } else {
        int idx = (blockIdx.x - NTOK) * 256 + tid;
        int seg = idx / NDD16;
        int off = idx - seg * NDD16;
        const float* src = (seg == 0) ? s0 : (seg == 1) ? s1 : (seg == 2) ? s2 : s3;
        __half* dst      = (seg == 0) ? d0 : (seg == 1) ? d1 : (seg == 2) ? d2 : d3;
        cvt16(src, dst, off);
    }
}

// ---------------------------------------------------------------------------
// RMSNorm (standalone, second norm): fp32 in -> fp16 out.
// ---------------------------------------------------------------------------
__global__ __launch_bounds__(256) void rmsnorm_kernel(
    const float* __restrict__ x, const float* __restrict__ g,
    __half* __restrict__ y)
{
    const int row = blockIdx.x;
    const int tid = threadIdx.x;
    const float* xr = x + (size_t)row * DMODEL;

    float4 v = *(const float4*)(xr + tid * 4);
    float ss = v.x * v.x + v.y * v.y + v.z * v.z + v.w * v.w;

    #pragma unroll
    for (int off = 16; off; off >>= 1)
        ss += __shfl_xor_sync(0xffffffffu, ss, off);

    __shared__ float red[8];
    const int lane = tid & 31, warp = tid >> 5;
    if (lane == 0) red[warp] = ss;
    __syncthreads();
    if (warp == 0) {
        float t = (lane < 8) ? red[lane] : 0.0f;
        #pragma unroll
        for (int off = 4; off; off >>= 1)
            t += __shfl_xor_sync(0xffffffffu, t, off);
        if (lane == 0) red[0] = t;
    }
    __syncthreads();

    const float inv = rsqrtf(red[0] * (1.0f / DMODEL) + 1e-5f);
    float4 gv = *(const float4*)(g + tid * 4);
    __half2 h0 = __floats2half2_rn(v.x * inv * gv.x, v.y * inv * gv.y);
    __half2 h1 = __floats2half2_rn(v.z * inv * gv.z, v.w * inv * gv.w);
    __half* yp = y + (size_t)row * DMODEL + tid * 4;
    *(__half2*)(yp)     = h0;
    *(__half2*)(yp + 2) = h1;
}

// ---------------------------------------------------------------------------
// FP16 tensor-core GEMM (R11 config) + optional z==3 convert slice.
// BM=BN=128, BK=64, 256 threads (8 warps 2x4), warp tile 64x32,
// 3-stage cp.async, one sync per k-tile, 2 CTAs/SM.
// z<3: GEMM with B/C selected by z. z==3 (QKV launch only): convert FF weights.
// ---------------------------------------------------------------------------
#define GF_STAGE_H (128 * 64)
#define GF_SMEM (6 * GF_STAGE_H * 2)     // 98304 bytes

template <int MODE>
__global__ __launch_bounds__(256, 2) void gemm_f16(
    const __half* __restrict__ A,
    const __half* __restrict__ B0, const __half* __restrict__ B1, const __half* __restrict__ B2,
    const float* __restrict__ R,
    void* __restrict__ C0v, void* __restrict__ C1v, void* __restrict__ C2v,
    int M, int N, int K,
    const float* __restrict__ S4, const float* __restrict__ S5, const float* __restrict__ S6,
    __half* __restrict__ D4, __half* __restrict__ D5, __half* __restrict__ D6)
{
    extern __shared__ __half smh[];
    __half* As = smh;
    __half* Bs = smh + 3 * GF_STAGE_H;

    const int z = blockIdx.z;
    const int tid  = threadIdx.x;

    // ---- co-scheduled FF-weight convert slice (256 blocks x 12 units) ----
    if (MODE == 0 && z == 3) {
        int blk = blockIdx.y * (int)gridDim.x + blockIdx.x;   // 0..255
        #pragma unroll
        for (int u = 0; u < 12; ++u) {
            int idx = (blk * 12 + u) * 256 + tid;             // 0..786431
            int seg = idx / NFF16;
            int off = idx - seg * NFF16;
            const float* src = (seg == 0) ? S4 : (seg == 1) ? S5 : S6;
            __half* dst      = (seg == 0) ? D4 : (seg == 1) ? D5 : D6;
            cvt16(src, dst, off);
        }
        return;
    }

    const __half* B = (z == 0) ? B0 : (z == 1) ? B1 : B2;
    void*         Cv = (z == 0) ? C0v : (z == 1) ? C1v : C2v;

    const int lane = tid & 31, warp = tid >> 5;
    const int g = lane >> 2, t4 = lane & 3;
    const int wm = warp >> 2, wn = warp & 3;
    const int bm = blockIdx.y, bn = blockIdx.x;

    const int lr = lane & 15;
    const int lc = (lane >> 4) << 3;
    const int sft = lane >> 3;

    const __half* Ab = A + (size_t)bm * 128 * K;
    const __half* Bb = B + (size_t)bn * 128 * K;

    float acc[4][4][4];
    #pragma unroll
    for (int i = 0; i < 4; ++i)
        #pragma unroll
        for (int j = 0; j < 4; ++j)
            #pragma unroll
            for (int r = 0; r < 4; ++r) acc[i][j][r] = 0.0f;

    const int T = K >> 6;

    auto load_tile = [&](int kt, int st) {
        const __half* Asrc = Ab + kt * 64;
        const __half* Bsrc = Bb + kt * 64;
        __half* Adst = As + st * GF_STAGE_H;
        __half* Bdst = Bs + st * GF_STAGE_H;
        #pragma unroll
        for (int e = 0; e < 4; ++e) {
            int id  = e * 256 + tid;
            int row = id >> 3;
            int c16 = id & 7;
            unsigned int sw = (unsigned int)(row * 128) + (((unsigned int)c16 ^ ((unsigned int)row & 7u)) * 16u);
            unsigned int sa = (unsigned int)__cvta_generic_to_shared((const char*)Adst + sw);
            asm volatile("cp.async.cg.shared.global [%0], [%1], 16;\n"
                         :: "r"(sa), "l"(Asrc + (size_t)row * K + c16 * 8));
            unsigned int sb = (unsigned int)__cvta_generic_to_shared((const char*)Bdst + sw);
            asm volatile("cp.async.cg.shared.global [%0], [%1], 16;\n"
                         :: "r"(sb), "l"(Bsrc + (size_t)row * K + c16 * 8));
        }
        asm volatile("cp.async.commit_group;\n");
    };

    load_tile(0, 0);
    load_tile(1, 1);

    for (int kt = 0; kt < T; ++kt) {
        if (kt + 1 < T) asm volatile("cp.async.wait_group 1;\n");
        else            asm volatile("cp.async.wait_group 0;\n");
        __syncthreads();

        if (kt + 2 < T) load_tile(kt + 2, (kt + 2) % 3);

        const __half* Asb = As + (kt % 3) * GF_STAGE_H;
        const __half* Bsb = Bs + (kt % 3) * GF_STAGE_H;

        #pragma unroll
        for (int ks = 0; ks < 4; ++ks) {
            const int k0 = ks * 16;
            unsigned int af[4][4], bf[2][4];
            #pragma unroll
            for (int i = 0; i < 4; ++i)
                ldsm4h(af[i], swp(Asb, wm * 64 + i * 16 + lr, k0 + lc));
            #pragma unroll
            for (int jp = 0; jp < 2; ++jp)
                ldsm4h(bf[jp], swp(Bsb, wn * 32 + 8 * (2 * jp + (sft >> 1)) + (lane & 7),
                                   k0 + ((sft & 1) << 3)));
            #pragma unroll
            for (int i = 0; i < 4; ++i)
                #pragma unroll
                for (int jp = 0; jp < 2; ++jp) {
                    mma_f16(acc[i][2 * jp],     af[i], bf[jp]);
                    mma_f16(acc[i][2 * jp + 1], af[i], bf[jp] + 2);
                }
        }
    }

    #pragma unroll
    for (int i = 0; i < 4; ++i) {
        const int r0 = bm * 128 + wm * 64 + i * 16 + g;
        #pragma unroll
        for (int j = 0; j < 4; ++j) {
            const int c0 = bn * 128 + wn * 32 + j * 8 + 2 * t4;
            if (MODE == 1) {
                float* C = (float*)Cv;
                float2 rr0 = *(const float2*)(R + (size_t)r0 * N + c0);
                float2 rr1 = *(const float2*)(R + (size_t)(r0 + 8) * N + c0);
                *(float2*)(C + (size_t)r0 * N + c0) =
                    make_float2(acc[i][j][0] + rr0.x, acc[i][j][1] + rr0.y);
                *(float2*)(C + (size_t)(r0 + 8) * N + c0) =
                    make_float2(acc[i][j][2] + rr1.x, acc[i][j][3] + rr1.y);
            } else {
                __half* C = (__half*)Cv;
                *(__half2*)(C + (size_t)r0 * N + c0) =
                    __floats2half2_rn(acc[i][j][0], acc[i][j][1]);
                *(__half2*)(C + (size_t)(r0 + 8) * N + c0) =
                    __floats2half2_rn(acc[i][j][2], acc[i][j][3]);
            }
        }
    }
}

// ---------------------------------------------------------------------------
// Fused W1/W3/SwiGLU GEMM (unchanged).
// ---------------------------------------------------------------------------
#define GS_A_H (128 * 64)
#define GS_B_H (64 * 64)
#define GS_SMEM ((3 * GS_A_H + 6 * GS_B_H) * 2)   // 98304 bytes

__global__ __launch_bounds__(256, 2) void gemm_swiglu(
    const __half* __restrict__ A,
    const __half* __restrict__ W1p, const __half* __restrict__ W3p,
    __half* __restrict__ Out, int K)
{
    extern __shared__ __half smh[];
    __half* As  = smh;
    __half* B1s = smh + 3 * GS_A_H;
    __half* B3s = B1s + 3 * GS_B_H;

    const int tid  = threadIdx.x;
    const int lane = tid & 31, warp = tid >> 5;
    const int g = lane >> 2, t4 = lane & 3;
    const int wm = warp >> 1, wn = warp & 1;
    const int bm = blockIdx.y, bn = blockIdx.x;

    const int lr = lane & 15;
    const int lc = (lane >> 4) << 3;
    const int sft = lane >> 3;

    const __half* Ab  = A   + (size_t)bm * 128 * K;
    const __half* B1b = W1p + (size_t)bn * 64 * K;
    const __half* B3b = W3p + (size_t)bn * 64 * K;

    float acc1[2][4][4], acc3[2][4][4];
    #pragma unroll
    for (int i = 0; i < 2; ++i)
        #pragma unroll
        for (int j = 0; j < 4; ++j)
            #pragma unroll
            for (int r = 0; r < 4; ++r) { acc1[i][j][r] = 0.0f; acc3[i][j][r] = 0.0f; }

    const int T = K >> 6;

    auto load_tile = [&](int kt, int st) {
        const __half* Asrc  = Ab  + kt * 64;
        const __half* B1src = B1b + kt * 64;
        const __half* B3src = B3b + kt * 64;
        __half* Adst  = As  + st * GS_A_H;
        __half* B1dst = B1s + st * GS_B_H;
        __half* B3dst = B3s + st * GS_B_H;
        #pragma unroll
        for (int e = 0; e < 4; ++e) {
            int id  = e * 256 + tid;
            int row = id >> 3;
            int c16 = id & 7;
            unsigned int sw = (unsigned int)(row * 128) + (((unsigned int)c16 ^ ((unsigned int)row & 7u)) * 16u);
            unsigned int sa = (unsigned int)__cvta_generic_to_shared((const char*)Adst + sw);
            asm volatile("cp.async.cg.shared.global [%0], [%1], 16;\n"
                         :: "r"(sa), "l"(Asrc + (size_t)row * K + c16 * 8));
        }
        #pragma unroll
        for (int e = 0; e < 2; ++e) {
            int id  = e * 256 + tid;
            int row = id >> 3;
            int c16 = id & 7;
            unsigned int sw = (unsigned int)(row * 128) + (((unsigned int)c16 ^ ((unsigned int)row & 7u)) * 16u);
            unsigned int s1 = (unsigned int)__cvta_generic_to_shared((const char*)B1dst + sw);
            asm volatile("cp.async.cg.shared.global [%0], [%1], 16;\n"
                         :: "r"(s1), "l"(B1src + (size_t)row * K + c16 * 8));
            unsigned int s3 = (unsigned int)__cvta_generic_to_shared((const char*)B3dst + sw);
            asm volatile("cp.async.cg.shared.global [%0], [%1], 16;\n"
                         :: "r"(s3), "l"(B3src + (size_t)row * K + c16 * 8));
        }
        asm volatile("cp.async.commit_group;\n");
    };

    load_tile(0, 0);
    load_tile(1, 1);

    for (int kt = 0; kt < T; ++kt) {
        if (kt + 1 < T) asm volatile("cp.async.wait_group 1;\n");
        else            asm volatile("cp.async.wait_group 0;\n");
        __syncthreads();

        if (kt + 2 < T) load_tile(kt + 2, (kt + 2) % 3);

        const __half* Asb  = As  + (kt % 3) * GS_A_H;
        const __half* B1sb = B1s + (kt % 3) * GS_B_H;
        const __half* B3sb = B3s + (kt % 3) * GS_B_H;

        #pragma unroll
        for (int ks = 0; ks < 4; ++ks) {
            const int k0 = ks * 16;
            unsigned int af[2][4], b1f[2][4], b3f[2][4];
            #pragma unroll
            for (int i = 0; i < 2; ++i)
                ldsm4h(af[i], swp(Asb, wm * 32 + i * 16 + lr, k0 + lc));
            #pragma unroll
            for (int jp = 0; jp < 2; ++jp) {
                const int brow = wn * 32 + 8 * (2 * jp + (sft >> 1)) + (lane & 7);
                const int bcol = k0 + ((sft & 1) << 3);
                ldsm4h(b1f[jp], swp(B1sb, brow, bcol));
                ldsm4h(b3f[jp], swp(B3sb, brow, bcol));
            }
            #pragma unroll
            for (int i = 0; i < 2; ++i)
                #pragma unroll
                for (int jp = 0; jp < 2; ++jp) {
                    mma_f16(acc1[i][2 * jp],     af[i], b1f[jp]);
                    mma_f16(acc1[i][2 * jp + 1], af[i], b1f[jp] + 2);
                    mma_f16(acc3[i][2 * jp],     af[i], b3f[jp]);
                    mma_f16(acc3[i][2 * jp + 1], af[i], b3f[jp] + 2);
                }
        }
    }

    #pragma unroll
    for (int i = 0; i < 2; ++i) {
        const int r0 = bm * 128 + wm * 32 + i * 16 + g;
        #pragma unroll
        for (int j = 0; j < 4; ++j) {
            const int c0 = bn * 64 + wn * 32 + j * 8 + 2 * t4;
            float o0 = acc1[i][j][0] * (1.0f / (1.0f + __expf(-acc1[i][j][0]))) * acc3[i][j][0];
            float o1 = acc1[i][j][1] * (1.0f / (1.0f + __expf(-acc1[i][j][1]))) * acc3[i][j][1];
            float o2 = acc1[i][j][2] * (1.0f / (1.0f + __expf(-acc1[i][j][2]))) * acc3[i][j][2];
            float o3 = acc1[i][j][3] * (1.0f / (1.0f + __expf(-acc1[i][j][3]))) * acc3[i][j][3];
            *(__half2*)(Out + (size_t)r0 * DFF + c0)       = __floats2half2_rn(o0, o1);
            *(__half2*)(Out + (size_t)(r0 + 8) * DFF + c0) = __floats2half2_rn(o2, o3);
        }
    }
}

// ---------------------------------------------------------------------------
// Flash attention v4 (clean 32-row grid). Grid: (S/128, B*H).
// ---------------------------------------------------------------------------
#define FA_Q_BYTES (128 * 128)
#define FA_KV_BYTES (64 * 128)
#define FA_SMEM_BYTES (FA_Q_BYTES + 6 * FA_KV_BYTES)   // 65536

__global__ __launch_bounds__(256) void flash_attn_kernel(
    const __half* __restrict__ Q, const __half* __restrict__ K,
    const __half* __restrict__ V, __half* __restrict__ O)
{
    extern __shared__ char smraw[];
    __half* Qs = (__half*)smraw;

    const int tid  = threadIdx.x;
    const int lane = tid & 31, w = tid >> 5;
    const int g = lane >> 2, t4 = lane & 3;
    const int lr = lane & 15;
    const int lc = (lane >> 4) << 3;

    const int qb = (int)gridDim.x - 1 - (int)blockIdx.x;
    const int bh = blockIdx.y;
    const int b = bh >> 4, h = bh & 15;

    const size_t base = ((size_t)b * SEQ) * DMODEL + h * DHEAD;
    const __half* Qg = Q + base + (size_t)(qb * 128) * DMODEL;
    const __half* Kg = K + base;
    const __half* Vg = V + base;

    #pragma unroll
    for (int e = 0; e < 4; ++e) {
        int id  = e * 256 + tid;
        int row = id >> 3;
        int c16 = id & 7;
        unsigned int sw = (unsigned int)(row * 128) + (((unsigned int)c16 ^ ((unsigned int)row & 7u)) * 16u);
        unsigned int sa = (unsigned int)__cvta_generic_to_shared(smraw + sw);
        asm volatile("cp.async.cg.shared.global [%0], [%1], 16;\n"
                     :: "r"(sa), "l"(Qg + (size_t)row * DMODEL + c16 * 8));
    }
    asm volatile("cp.async.commit_group;\n");

    auto load_kv = [&](int t, int buf) {
        const __half* Ksrc = Kg + (size_t)(t * 64) * DMODEL;
        const __half* Vsrc = Vg + (size_t)(t * 64) * DMODEL;
        char* Kdst = smraw + FA_Q_BYTES + buf * FA_KV_BYTES;
        char* Vdst = smraw + FA_Q_BYTES + 3 * FA_KV_BYTES + buf * FA_KV_BYTES;
        #pragma unroll
        for (int e = 0; e < 2; ++e) {
            int id  = e * 256 + tid;
            int row = id >> 3;
            int c16 = id & 7;
            unsigned int sw = (unsigned int)(row * 128) + (((unsigned int)c16 ^ ((unsigned int)row & 7u)) * 16u);
            unsigned int sk = (unsigned int)__cvta_generic_to_shared(Kdst + sw);
            asm volatile("cp.async.cg.shared.global [%0], [%1], 16;\n"
                         :: "r"(sk), "l"(Ksrc + (size_t)row * DMODEL + c16 * 8));
            unsigned int sv = (unsigned int)__cvta_generic_to_shared(Vdst + sw);
            asm volatile("cp.async.cg.shared.global [%0], [%1], 16;\n"
                         :: "r"(sv), "l"(Vsrc + (size_t)row * DMODEL + c16 * 8));
        }
        asm volatile("cp.async.commit_group;\n");
    };

    load_kv(0, 0);
    load_kv(1, 1);

    asm volatile("cp.async.wait_group 2;\n");
    __syncthreads();

    unsigned int aq[4][4];
    #pragma unroll
    for (int dt = 0; dt < 4; ++dt)
        ldsm4h(aq[dt], swp(Qs, 16 * w + lr, dt * 16 + lc));

    float o_acc[8][4];
    #pragma unroll
    for (int j = 0; j < 8; ++j)
        #pragma unroll
        for (int r = 0; r < 4; ++r) o_acc[j][r] = 0.0f;

    float m0 = -INFINITY, m1 = -INFINITY, l0 = 0.0f, l1 = 0.0f;

    const float CE = 0.125f * 1.44269504f;
    const unsigned int bones[2] = {0x3C003C00u, 0x3C003C00u};

    const int T = 2 * qb + 2;

    for (int t = 0; t < T; ++t) {
        if (t + 1 < T) asm volatile("cp.async.wait_group 1;\n");
        else           asm volatile("cp.async.wait_group 0;\n");
        __syncthreads();

        if (t + 2 < T) load_kv(t + 2, (t + 2) % 3);

        const bool skip = (16 * w + 15) < (64 * t - 128 * qb);
        if (!skip) {
            const __half* Ksb = (const __half*)(smraw + FA_Q_BYTES + (t % 3) * FA_KV_BYTES);
            const __half* Vsb = (const __half*)(smraw + FA_Q_BYTES + 3 * FA_KV_BYTES + (t % 3) * FA_KV_BYTES);

            float s[8][4];
            #pragma unroll
            for (int j = 0; j < 8; ++j)
                #pragma unroll
                for (int r = 0; r < 4; ++r) s[j][r] = 0.0f;

            const int sft = lane >> 3;
            #pragma unroll
            for (int dt = 0; dt < 4; ++dt) {
                #pragma unroll
                for (int jp = 0; jp < 4; ++jp) {
                    unsigned int bk[4];
                    ldsm4h(bk, swp(Ksb, 8 * (2 * jp + (sft >> 1)) + (lane & 7),
                                   dt * 16 + ((sft & 1) << 3)));
                    mma_f16(s[2 * jp],     aq[dt], bk);
                    mma_f16(s[2 * jp + 1], aq[dt], bk + 2);
                }
            }

            if (t >= 2 * qb) {
                const int q0r = 128 * qb + 16 * w + g;
                #pragma unroll
                for (int j = 0; j < 8; ++j) {
                    const int kk = 64 * t + 8 * j + 2 * t4;
                    if (kk     > q0r)     s[j][0] = -INFINITY;
                    if (kk + 1 > q0r)     s[j][1] = -INFINITY;
                    if (kk     > q0r + 8) s[j][2] = -INFINITY;
                    if (kk + 1 > q0r + 8) s[j][3] = -INFINITY;
                }
            }

            float mt0 = -INFINITY, mt1 = -INFINITY;
            #pragma unroll
            for (int j = 0; j < 8; ++j) {
                mt0 = fmaxf(mt0, fmaxf(s[j][0], s[j][1]));
                mt1 = fmaxf(mt1, fmaxf(s[j][2], s[j][3]));
            }
            mt0 = fmaxf(mt0, __shfl_xor_sync(0xffffffffu, mt0, 1));
            mt0 = fmaxf(mt0, __shfl_xor_sync(0xffffffffu, mt0, 2));
            mt1 = fmaxf(mt1, __shfl_xor_sync(0xffffffffu, mt1, 1));
            mt1 = fmaxf(mt1, __shfl_xor_sync(0xffffffffu, mt1, 2));

            const float mn0 = fmaxf(m0, mt0);
            const float mn1 = fmaxf(m1, mt1);
            const float sc0 = ex2f((m0 - mn0) * CE);
            const float sc1 = ex2f((m1 - mn1) * CE);
            const float bexp0 = mn0 * CE;
            const float bexp1 = mn1 * CE;

            unsigned int ap[4][4];
            #pragma unroll
            for (int j = 0; j < 8; ++j) {
                float d0 = fmaf(s[j][0], CE, -bexp0);
                float d1 = fmaf(s[j][1], CE, -bexp0);
                float d2 = fmaf(s[j][2], CE, -bexp1);
                float d3 = fmaf(s[j][3], CE, -bexp1);
                __half2 e01 = h2exp2(__floats2half2_rn(d0, d1));
                __half2 e23 = h2exp2(__floats2half2_rn(d2, d3));
                const int kt = j >> 1;
                if ((j & 1) == 0) {
                    ap[kt][0] = *(unsigned int*)&e01;
                    ap[kt][1] = *(unsigned int*)&e23;
                } else {
                    ap[kt][2] = *(unsigned int*)&e01;
                    ap[kt][3] = *(unsigned int*)&e23;
                }
            }

            float sm[4] = {0.0f, 0.0f, 0.0f, 0.0f};
            #pragma unroll
            for (int kt = 0; kt < 4; ++kt)
                mma_f16(sm, ap[kt], bones);

            l0 = l0 * sc0 + sm[0];
            l1 = l1 * sc1 + sm[2];
            m0 = mn0;
            m1 = mn1;

            #pragma unroll
            for (int j = 0; j < 8; ++j) {
                o_acc[j][0] *= sc0; o_acc[j][1] *= sc0;
                o_acc[j][2] *= sc1; o_acc[j][3] *= sc1;
            }

            #pragma unroll
            for (int kt = 0; kt < 4; ++kt) {
                #pragma unroll
                for (int jp = 0; jp < 4; ++jp) {
                    unsigned int bv[4];
                    ldsm4ht(bv, swp(Vsb, 16 * kt + ((sft & 1) << 3) + (lane & 7),
                                    16 * jp + ((sft >> 1) << 3)));
                    mma_f16(o_acc[2 * jp],     ap[kt], bv);
                    mma_f16(o_acc[2 * jp + 1], ap[kt], bv + 2);
                }
            }
        }
    }

    const float inv0 = 1.0f / l0;
    const float inv1 = 1.0f / l1;
    __half* Og = O + base + (size_t)(qb * 128 + 16 * w) * DMODEL;
    #pragma unroll
    for (int j = 0; j < 8; ++j) {
        const int d = 8 * j + 2 * t4;
        *(__half2*)(Og + (size_t)g * DMODEL + d) =
            __floats2half2_rn(o_acc[j][0] * inv0, o_acc[j][1] * inv0);
        *(__half2*)(Og + (size_t)(g + 8) * DMODEL + d) =
            __floats2half2_rn(o_acc[j][2] * inv1, o_acc[j][3] * inv1);
    }
}

// ---------------------------------------------------------------------------
// Launch
// ---------------------------------------------------------------------------
extern "C" void kernel_launch(void* const* d_in, const int* in_sizes, int n_in,
                              void* d_out, int out_size)
{
    const float* x  = (const float*)d_in[0];
    const float* Wq = (const float*)d_in[1];
    const float* Wk = (const float*)d_in[2];
    const float* Wv = (const float*)d_in[3];
    const float* Wo = (const float*)d_in[4];
    const float* W1 = (const float*)d_in[5];
    const float* W2 = (const float*)d_in[6];
    const float* W3 = (const float*)d_in[7];
    const float* g1 = (const float*)d_in[8];
    const float* g2 = (const float*)d_in[9];
    float* out = (float*)d_out;

    __half *h1, *q, *k, *v, *o, *a;
    __half *wq, *wk, *wv, *wo, *w1, *w2, *w3;
    float *x2;
    cudaGetSymbolAddress((void**)&h1, g_h1);
    cudaGetSymbolAddress((void**)&q,  g_q);
    cudaGetSymbolAddress((void**)&k,  g_k);
    cudaGetSymbolAddress((void**)&v,  g_v);
    cudaGetSymbolAddress((void**)&o,  g_o);
    cudaGetSymbolAddress((void**)&x2, g_x2);
    cudaGetSymbolAddress((void**)&a,  g_a);
    cudaGetSymbolAddress((void**)&wq, g_wq);
    cudaGetSymbolAddress((void**)&wk, g_wk);
    cudaGetSymbolAddress((void**)&wv, g_wv);
    cudaGetSymbolAddress((void**)&wo, g_wo);
    cudaGetSymbolAddress((void**)&w1, g_w1);
    cudaGetSymbolAddress((void**)&w2, g_w2);
    cudaGetSymbolAddress((void**)&w3, g_w3);

    cudaFuncSetAttribute(flash_attn_kernel,
                         cudaFuncAttributeMaxDynamicSharedMemorySize, FA_SMEM_BYTES);
    cudaFuncSetAttribute(gemm_f16<0>,
                         cudaFuncAttributeMaxDynamicSharedMemorySize, GF_SMEM);
    cudaFuncSetAttribute(gemm_f16<1>,
                         cudaFuncAttributeMaxDynamicSharedMemorySize, GF_SMEM);
    cudaFuncSetAttribute(gemm_swiglu,
                         cudaFuncAttributeMaxDynamicSharedMemorySize, GS_SMEM);

    const dim3 gemm_qkv(DMODEL / 128, NTOK / 128, 4);   // z=3: FF weight convert
    const dim3 gemm_d_d(DMODEL / 128, NTOK / 128, 1);
    const dim3 gemm_sw(DFF / 64, NTOK / 128);

    // 0+1) fused: dd-weight convert + h1 = rmsnorm(x, g1)
    prelude_kernel<<<NTOK + NDDCVT, 256>>>(x, g1, h1,
                                           Wq, Wk, Wv, Wo,
                                           wq, wk, wv, wo);

    // 2) q,k,v = h1 @ W{q,k,v}^T  +  co-scheduled FF-weight convert (z==3)
    gemm_f16<0><<<gemm_qkv, 256, GF_SMEM>>>(h1, wq, wk, wv, nullptr,
                                            q, k, v, NTOK, DMODEL, DMODEL,
                                            W1, W2, W3, w1, w2, w3);

    // 3) o = causal_attention(q, k, v)
    dim3 fa_grid(SEQ / 128, BATCH * NHEADS);
    flash_attn_kernel<<<fa_grid, 256, FA_SMEM_BYTES>>>(q, k, v, o);

    // 4) x2 = x + o @ Wo^T (fp32 out)
    gemm_f16<1><<<gemm_d_d, 256, GF_SMEM>>>(o, wo, wo, wo, x,
                                            x2, x2, x2, NTOK, DMODEL, DMODEL,
                                            nullptr, nullptr, nullptr,
                                            nullptr, nullptr, nullptr);

    // 5) h2 = rmsnorm(x2, g2) -> fp16
    rmsnorm_kernel<<<NTOK, 256>>>(x2, g2, h1);

    // 6) a = silu(h2 @ W1^T) * (h2 @ W3^T)   (fused)
    gemm_swiglu<<<gemm_sw, 256, GS_SMEM>>>(h1, w1, w3, a, DMODEL);

    // 7) out = x2 + a @ W2^T (fp32 out)
    gemm_f16<1><<<gemm_d_d, 256, GF_SMEM>>>(a, w2, w2, w2, x2,
                                            out, out, out, NTOK, DMODEL, DFF,
                                            nullptr, nullptr, nullptr,
                                            nullptr, nullptr, nullptr);
}

// round 16
// speedup vs baseline: 1.0015x; 1.0015x over previous
#include <cuda_runtime.h>
#include <cuda_fp16.h>
#include <stdint.h>
#include <math.h>

// Problem constants
#define BATCH 2
#define SEQ 2048
#define DMODEL 1024
#define NHEADS 16
#define DHEAD 64
#define DFF 4096
#define NTOK (BATCH * SEQ)   // 4096

// ---------------------------------------------------------------------------
// Scratch (device globals; allocation is forbidden)
// ---------------------------------------------------------------------------
__device__ __half g_h1[NTOK * DMODEL];
__device__ __half g_q [NTOK * DMODEL];
__device__ __half g_k [NTOK * DMODEL];
__device__ __half g_v [NTOK * DMODEL];
__device__ __half g_o [NTOK * DMODEL];
__device__ float  g_x2[NTOK * DMODEL];
__device__ __half g_a [NTOK * DFF];
// fp16 weights
__device__ __half g_wq[DMODEL * DMODEL];
__device__ __half g_wk[DMODEL * DMODEL];
__device__ __half g_wv[DMODEL * DMODEL];
__device__ __half g_wo[DMODEL * DMODEL];
__device__ __half g_w1[DFF * DMODEL];
__device__ __half g_w2[DMODEL * DFF];
__device__ __half g_w3[DFF * DMODEL];

// ---------------------------------------------------------------------------
// mma.sync helpers
// ---------------------------------------------------------------------------
__device__ __forceinline__ void mma_f16(float* c, const unsigned int* a, const unsigned int* b) {
    asm volatile(
        "mma.sync.aligned.m16n8k16.row.col.f32.f16.f16.f32 "
        "{%0,%1,%2,%3}, {%4,%5,%6,%7}, {%8,%9}, {%0,%1,%2,%3};"
        : "+f"(c[0]), "+f"(c[1]), "+f"(c[2]), "+f"(c[3])
        : "r"(a[0]), "r"(a[1]), "r"(a[2]), "r"(a[3]), "r"(b[0]), "r"(b[1]));
}
__device__ __forceinline__ void ldsm4h(unsigned int* r, const __half* p) {
    unsigned int addr = (unsigned int)__cvta_generic_to_shared(p);
    asm volatile("ldmatrix.sync.aligned.m8n8.x4.shared.b16 {%0,%1,%2,%3}, [%4];"
                 : "=r"(r[0]), "=r"(r[1]), "=r"(r[2]), "=r"(r[3]) : "r"(addr));
}
__device__ __forceinline__ void ldsm4ht(unsigned int* r, const __half* p) {
    unsigned int addr = (unsigned int)__cvta_generic_to_shared(p);
    asm volatile("ldmatrix.sync.aligned.m8n8.x4.trans.shared.b16 {%0,%1,%2,%3}, [%4];"
                 : "=r"(r[0]), "=r"(r[1]), "=r"(r[2]), "=r"(r[3]) : "r"(addr));
}
__device__ __forceinline__ float ex2f(float x) {
    float y;
    asm("ex2.approx.ftz.f32 %0, %1;" : "=f"(y) : "f"(x));
    return y;
}

// SW128 swizzled pointer within a [rows x 128 bytes] tile. halfcol multiple of 8.
__device__ __forceinline__ const __half* swp(const __half* base, int row, int halfcol) {
    unsigned int off = (unsigned int)(row * 128) +
        (((unsigned int)(halfcol * 2)) ^ (((unsigned int)row & 7u) * 16u));
    return (const __half*)((const char*)base + off);
}

// convert helper: 16 floats -> 16 halfs at unit index `off`
__device__ __forceinline__ void cvt16(const float* __restrict__ src,
                                      __half* __restrict__ dst, int off) {
    float4 v0 = *(const float4*)(src + (size_t)off * 16);
    float4 v1 = *(const float4*)(src + (size_t)off * 16 + 4);
    float4 v2 = *(const float4*)(src + (size_t)off * 16 + 8);
    float4 v3 = *(const float4*)(src + (size_t)off * 16 + 12);
    __half2 h[8];
    h[0] = __floats2half2_rn(v0.x, v0.y);
    h[1] = __floats2half2_rn(v0.z, v0.w);
    h[2] = __floats2half2_rn(v1.x, v1.y);
    h[3] = __floats2half2_rn(v1.z, v1.w);
    h[4] = __floats2half2_rn(v2.x, v2.y);
    h[5] = __floats2half2_rn(v2.z, v2.w);
    h[6] = __floats2half2_rn(v3.x, v3.y);
    h[7] = __floats2half2_rn(v3.z, v3.w);
    *(uint4*)(dst + (size_t)off * 16)     = ((uint4*)h)[0];
    *(uint4*)(dst + (size_t)off * 16 + 8) = ((uint4*)h)[1];
}

// ---------------------------------------------------------------------------
// Prelude: rmsnorm1 + converts for Wq,Wk,Wv (the QKV critical path only).
// Wo + W2 convert in the attention launch; W1 + W3 in the QKV launch (z==3).
// ---------------------------------------------------------------------------
#define NDD16 (DMODEL * DMODEL / 16)   // 65536
#define NFF16 (DFF * DMODEL / 16)      // 262144
#define NQKVCVT (3 * NDD16 / 256)      // 768 blocks

__global__ __launch_bounds__(256) void prelude_kernel(
    const float* __restrict__ x, const float* __restrict__ g1,
    __half* __restrict__ h1,
    const float* __restrict__ s0, const float* __restrict__ s1,
    const float* __restrict__ s2,
    __half* __restrict__ d0, __half* __restrict__ d1,
    __half* __restrict__ d2)
{
    const int tid = threadIdx.x;

    if (blockIdx.x < NTOK) {
        const int row = blockIdx.x;
        const float* xr = x + (size_t)row * DMODEL;

        float4 v = *(const float4*)(xr + tid * 4);
        float ss = v.x * v.x + v.y * v.y + v.z * v.z + v.w * v.w;

        #pragma unroll
        for (int off = 16; off; off >>= 1)
            ss += __shfl_xor_sync(0xffffffffu, ss, off);

        __shared__ float red[8];
        const int lane = tid & 31, warp = tid >> 5;
        if (lane == 0) red[warp] = ss;
        __syncthreads();
        if (warp == 0) {
            float t = (lane < 8) ? red[lane] : 0.0f;
            #pragma unroll
            for (int off = 4; off; off >>= 1)
                t += __shfl_xor_sync(0xffffffffu, t, off);
            if (lane == 0) red[0] = t;
        }
        __syncthreads();

        const float inv = rsqrtf(red[0] * (1.0f / DMODEL) + 1e-5f);
        float4 gv = *(const float4*)(g1 + tid * 4);
        __half2 h0 = __floats2half2_rn(v.x * inv * gv.x, v.y * inv * gv.y);
        __half2 hh = __floats2half2_rn(v.z * inv * gv.z, v.w * inv * gv.w);
        __half* yp = h1 + (size_t)row * DMODEL + tid * 4;
        *(__half2*)(yp)     = h0;
        *(__half2*)(yp + 2) = hh;
    } else {
        int idx = (blockIdx.x - NTOK) * 256 + tid;    // 0 .. 3*NDD16-1
        int seg = idx / NDD16;
        int off = idx - seg * NDD16;
        const float* src = (seg == 0) ? s0 : (seg == 1) ? s1 : s2;
        __half* dst      = (seg == 0) ? d0 : (seg == 1) ? d1 : d2;
        cvt16(src, dst, off);
    }
}

// ---------------------------------------------------------------------------
// RMSNorm (standalone, second norm): fp32 in -> fp16 out.
// ---------------------------------------------------------------------------
__global__ __launch_bounds__(256) void rmsnorm_kernel(
    const float* __restrict__ x, const float* __restrict__ g,
    __half* __restrict__ y)
{
    const int row = blockIdx.x;
    const int tid = threadIdx.x;
    const float* xr = x + (size_t)row * DMODEL;

    float4 v = *(const float4*)(xr + tid * 4);
    float ss = v.x * v.x + v.y * v.y + v.z * v.z + v.w * v.w;

    #pragma unroll
    for (int off = 16; off; off >>= 1)
        ss += __shfl_xor_sync(0xffffffffu, ss, off);

    __shared__ float red[8];
    const int lane = tid & 31, warp = tid >> 5;
    if (lane == 0) red[warp] = ss;
    __syncthreads();
    if (warp == 0) {
        float t = (lane < 8) ? red[lane] : 0.0f;
        #pragma unroll
        for (int off = 4; off; off >>= 1)
            t += __shfl_xor_sync(0xffffffffu, t, off);
        if (lane == 0) red[0] = t;
    }
    __syncthreads();

    const float inv = rsqrtf(red[0] * (1.0f / DMODEL) + 1e-5f);
    float4 gv = *(const float4*)(g + tid * 4);
    __half2 h0 = __floats2half2_rn(v.x * inv * gv.x, v.y * inv * gv.y);
    __half2 h1 = __floats2half2_rn(v.z * inv * gv.z, v.w * inv * gv.w);
    __half* yp = y + (size_t)row * DMODEL + tid * 4;
    *(__half2*)(yp)     = h0;
    *(__half2*)(yp + 2) = h1;
}

// ---------------------------------------------------------------------------
// FP16 tensor-core GEMM (R11 config) + optional z==3 convert slice (W1+W3).
// BM=BN=128, BK=64, 256 threads (8 warps 2x4), warp tile 64x32,
// 3-stage cp.async, one sync per k-tile, 2 CTAs/SM.
// ---------------------------------------------------------------------------
#define GF_STAGE_H (128 * 64)
#define GF_SMEM (6 * GF_STAGE_H * 2)     // 98304 bytes

template <int MODE>
__global__ __launch_bounds__(256, 2) void gemm_f16(
    const __half* __restrict__ A,
    const __half* __restrict__ B0, const __half* __restrict__ B1, const __half* __restrict__ B2,
    const float* __restrict__ R,
    void* __restrict__ C0v, void* __restrict__ C1v, void* __restrict__ C2v,
    int M, int N, int K,
    const float* __restrict__ S4, const float* __restrict__ S5,
    __half* __restrict__ D4, __half* __restrict__ D5)
{
    extern __shared__ __half smh[];
    __half* As = smh;
    __half* Bs = smh + 3 * GF_STAGE_H;

    const int z = blockIdx.z;
    const int tid  = threadIdx.x;

    // ---- co-scheduled convert slice: W1 + W3 (256 blocks x 8 units) ----
    if (MODE == 0 && z == 3) {
        int blk = blockIdx.y * (int)gridDim.x + blockIdx.x;   // 0..255
        #pragma unroll
        for (int u = 0; u < 8; ++u) {
            int idx = (blk * 8 + u) * 256 + tid;              // 0..524287
            int seg = idx / NFF16;
            int off = idx - seg * NFF16;
            const float* src = (seg == 0) ? S4 : S5;
            __half* dst      = (seg == 0) ? D4 : D5;
            cvt16(src, dst, off);
        }
        return;
    }

    const __half* B = (z == 0) ? B0 : (z == 1) ? B1 : B2;
    void*         Cv = (z == 0) ? C0v : (z == 1) ? C1v : C2v;

    const int lane = tid & 31, warp = tid >> 5;
    const int g = lane >> 2, t4 = lane & 3;
    const int wm = warp >> 2, wn = warp & 3;
    const int bm = blockIdx.y, bn = blockIdx.x;

    const int lr = lane & 15;
    const int lc = (lane >> 4) << 3;
    const int sft = lane >> 3;

    const __half* Ab = A + (size_t)bm * 128 * K;
    const __half* Bb = B + (size_t)bn * 128 * K;

    float acc[4][4][4];
    #pragma unroll
    for (int i = 0; i < 4; ++i)
        #pragma unroll
        for (int j = 0; j < 4; ++j)
            #pragma unroll
            for (int r = 0; r < 4; ++r) acc[i][j][r] = 0.0f;

    const int T = K >> 6;

    auto load_tile = [&](int kt, int st) {
        const __half* Asrc = Ab + kt * 64;
        const __half* Bsrc = Bb + kt * 64;
        __half* Adst = As + st * GF_STAGE_H;
        __half* Bdst = Bs + st * GF_STAGE_H;
        #pragma unroll
        for (int e = 0; e < 4; ++e) {
            int id  = e * 256 + tid;
            int row = id >> 3;
            int c16 = id & 7;
            unsigned int sw = (unsigned int)(row * 128) + (((unsigned int)c16 ^ ((unsigned int)row & 7u)) * 16u);
            unsigned int sa = (unsigned int)__cvta_generic_to_shared((const char*)Adst + sw);
            asm volatile("cp.async.cg.shared.global [%0], [%1], 16;\n"
                         :: "r"(sa), "l"(Asrc + (size_t)row * K + c16 * 8));
            unsigned int sb = (unsigned int)__cvta_generic_to_shared((const char*)Bdst + sw);
            asm volatile("cp.async.cg.shared.global [%0], [%1], 16;\n"
                         :: "r"(sb), "l"(Bsrc + (size_t)row * K + c16 * 8));
        }
        asm volatile("cp.async.commit_group;\n");
    };

    load_tile(0, 0);
    load_tile(1, 1);

    for (int kt = 0; kt < T; ++kt) {
        if (kt + 1 < T) asm volatile("cp.async.wait_group 1;\n");
        else            asm volatile("cp.async.wait_group 0;\n");
        __syncthreads();

        if (kt + 2 < T) load_tile(kt + 2, (kt + 2) % 3);

        const __half* Asb = As + (kt % 3) * GF_STAGE_H;
        const __half* Bsb = Bs + (kt % 3) * GF_STAGE_H;

        #pragma unroll
        for (int ks = 0; ks < 4; ++ks) {
            const int k0 = ks * 16;
            unsigned int af[4][4], bf[2][4];
            #pragma unroll
            for (int i = 0; i < 4; ++i)
                ldsm4h(af[i], swp(Asb, wm * 64 + i * 16 + lr, k0 + lc));
            #pragma unroll
            for (int jp = 0; jp < 2; ++jp)
                ldsm4h(bf[jp], swp(Bsb, wn * 32 + 8 * (2 * jp + (sft >> 1)) + (lane & 7),
                                   k0 + ((sft & 1) << 3)));
            #pragma unroll
            for (int i = 0; i < 4; ++i)
                #pragma unroll
                for (int jp = 0; jp < 2; ++jp) {
                    mma_f16(acc[i][2 * jp],     af[i], bf[jp]);
                    mma_f16(acc[i][2 * jp + 1], af[i], bf[jp] + 2);
                }
        }
    }

    #pragma unroll
    for (int i = 0; i < 4; ++i) {
        const int r0 = bm * 128 + wm * 64 + i * 16 + g;
        #pragma unroll
        for (int j = 0; j < 4; ++j) {
            const int c0 = bn * 128 + wn * 32 + j * 8 + 2 * t4;
            if (MODE == 1) {
                float* C = (float*)Cv;
                float2 rr0 = *(const float2*)(R + (size_t)r0 * N + c0);
                float2 rr1 = *(const float2*)(R + (size_t)(r0 + 8) * N + c0);
                *(float2*)(C + (size_t)r0 * N + c0) =
                    make_float2(acc[i][j][0] + rr0.x, acc[i][j][1] + rr0.y);
                *(float2*)(C + (size_t)(r0 + 8) * N + c0) =
                    make_float2(acc[i][j][2] + rr1.x, acc[i][j][3] + rr1.y);
            } else {
                __half* C = (__half*)Cv;
                *(__half2*)(C + (size_t)r0 * N + c0) =
                    __floats2half2_rn(acc[i][j][0], acc[i][j][1]);
                *(__half2*)(C + (size_t)(r0 + 8) * N + c0) =
                    __floats2half2_rn(acc[i][j][2], acc[i][j][3]);
            }
        }
    }
}

// ---------------------------------------------------------------------------
// Fused W1/W3/SwiGLU GEMM (unchanged).
// ---------------------------------------------------------------------------
#define GS_A_H (128 * 64)
#define GS_B_H (64 * 64)
#define GS_SMEM ((3 * GS_A_H + 6 * GS_B_H) * 2)   // 98304 bytes

__global__ __launch_bounds__(256, 2) void gemm_swiglu(
    const __half* __restrict__ A,
    const __half* __restrict__ W1p, const __half* __restrict__ W3p,
    __half* __restrict__ Out, int K)
{
    extern __shared__ __half smh[];
    __half* As  = smh;
    __half* B1s = smh + 3 * GS_A_H;
    __half* B3s = B1s + 3 * GS_B_H;

    const int tid  = threadIdx.x;
    const int lane = tid & 31, warp = tid >> 5;
    const int g = lane >> 2, t4 = lane & 3;
    const int wm = warp >> 1, wn = warp & 1;
    const int bm = blockIdx.y, bn = blockIdx.x;

    const int lr = lane & 15;
    const int lc = (lane >> 4) << 3;
    const int sft = lane >> 3;

    const __half* Ab  = A   + (size_t)bm * 128 * K;
    const __half* B1b = W1p + (size_t)bn * 64 * K;
    const __half* B3b = W3p + (size_t)bn * 64 * K;

    float acc1[2][4][4], acc3[2][4][4];
    #pragma unroll
    for (int i = 0; i < 2; ++i)
        #pragma unroll
        for (int j = 0; j < 4; ++j)
            #pragma unroll
            for (int r = 0; r < 4; ++r) { acc1[i][j][r] = 0.0f; acc3[i][j][r] = 0.0f; }

    const int T = K >> 6;

    auto load_tile = [&](int kt, int st) {
        const __half* Asrc  = Ab  + kt * 64;
        const __half* B1src = B1b + kt * 64;
        const __half* B3src = B3b + kt * 64;
        __half* Adst  = As  + st * GS_A_H;
        __half* B1dst = B1s + st * GS_B_H;
        __half* B3dst = B3s + st * GS_B_H;
        #pragma unroll
        for (int e = 0; e < 4; ++e) {
            int id  = e * 256 + tid;
            int row = id >> 3;
            int c16 = id & 7;
            unsigned int sw = (unsigned int)(row * 128) + (((unsigned int)c16 ^ ((unsigned int)row & 7u)) * 16u);
            unsigned int sa = (unsigned int)__cvta_generic_to_shared((const char*)Adst + sw);
            asm volatile("cp.async.cg.shared.global [%0], [%1], 16;\n"
                         :: "r"(sa), "l"(Asrc + (size_t)row * K + c16 * 8));
        }
        #pragma unroll
        for (int e = 0; e < 2; ++e) {
            int id  = e * 256 + tid;
            int row = id >> 3;
            int c16 = id & 7;
            unsigned int sw = (unsigned int)(row * 128) + (((unsigned int)c16 ^ ((unsigned int)row & 7u)) * 16u);
            unsigned int s1 = (unsigned int)__cvta_generic_to_shared((const char*)B1dst + sw);
            asm volatile("cp.async.cg.shared.global [%0], [%1], 16;\n"
                         :: "r"(s1), "l"(B1src + (size_t)row * K + c16 * 8));
            unsigned int s3 = (unsigned int)__cvta_generic_to_shared((const char*)B3dst + sw);
            asm volatile("cp.async.cg.shared.global [%0], [%1], 16;\n"
                         :: "r"(s3), "l"(B3src + (size_t)row * K + c16 * 8));
        }
        asm volatile("cp.async.commit_group;\n");
    };

    load_tile(0, 0);
    load_tile(1, 1);

    for (int kt = 0; kt < T; ++kt) {
        if (kt + 1 < T) asm volatile("cp.async.wait_group 1;\n");
        else            asm volatile("cp.async.wait_group 0;\n");
        __syncthreads();

        if (kt + 2 < T) load_tile(kt + 2, (kt + 2) % 3);

        const __half* Asb  = As  + (kt % 3) * GS_A_H;
        const __half* B1sb = B1s + (kt % 3) * GS_B_H;
        const __half* B3sb = B3s + (kt % 3) * GS_B_H;

        #pragma unroll
        for (int ks = 0; ks < 4; ++ks) {
            const int k0 = ks * 16;
            unsigned int af[2][4], b1f[2][4], b3f[2][4];
            #pragma unroll
            for (int i = 0; i < 2; ++i)
                ldsm4h(af[i], swp(Asb, wm * 32 + i * 16 + lr, k0 + lc));
            #pragma unroll
            for (int jp = 0; jp < 2; ++jp) {
                const int brow = wn * 32 + 8 * (2 * jp + (sft >> 1)) + (lane & 7);
                const int bcol = k0 + ((sft & 1) << 3);
                ldsm4h(b1f[jp], swp(B1sb, brow, bcol));
                ldsm4h(b3f[jp], swp(B3sb, brow, bcol));
            }
            #pragma unroll
            for (int i = 0; i < 2; ++i)
                #pragma unroll
                for (int jp = 0; jp < 2; ++jp) {
                    mma_f16(acc1[i][2 * jp],     af[i], b1f[jp]);
                    mma_f16(acc1[i][2 * jp + 1], af[i], b1f[jp] + 2);
                    mma_f16(acc3[i][2 * jp],     af[i], b3f[jp]);
                    mma_f16(acc3[i][2 * jp + 1], af[i], b3f[jp] + 2);
                }
        }
    }

    #pragma unroll
    for (int i = 0; i < 2; ++i) {
        const int r0 = bm * 128 + wm * 32 + i * 16 + g;
        #pragma unroll
        for (int j = 0; j < 4; ++j) {
            const int c0 = bn * 64 + wn * 32 + j * 8 + 2 * t4;
            float o0 = acc1[i][j][0] * (1.0f / (1.0f + __expf(-acc1[i][j][0]))) * acc3[i][j][0];
            float o1 = acc1[i][j][1] * (1.0f / (1.0f + __expf(-acc1[i][j][1]))) * acc3[i][j][1];
            float o2 = acc1[i][j][2] * (1.0f / (1.0f + __expf(-acc1[i][j][2]))) * acc3[i][j][2];
            float o3 = acc1[i][j][3] * (1.0f / (1.0f + __expf(-acc1[i][j][3]))) * acc3[i][j][3];
            *(__half2*)(Out + (size_t)r0 * DFF + c0)       = __floats2half2_rn(o0, o1);
            *(__half2*)(Out + (size_t)(r0 + 8) * DFF + c0) = __floats2half2_rn(o2, o3);
        }
    }
}

// ---------------------------------------------------------------------------
// Flash attention + co-scheduled convert of W2 and Wo.
// Grid: (16, 32 + 80). y<32: attention. y>=32: convert.
// ---------------------------------------------------------------------------
#define FA_Q_BYTES (128 * 128)
#define FA_KV_BYTES (64 * 128)
#define FA_SMEM_BYTES (FA_Q_BYTES + 6 * FA_KV_BYTES)   // 65536
#define FA_BH (BATCH * NHEADS)                          // 32
// W2: NFF16 units = 1024 blocks = 64 rows; Wo: NDD16 units = 256 blocks = 16 rows
#define FA_CVT_ROWS 80

__global__ __launch_bounds__(256) void flash_attn_kernel(
    const __half* __restrict__ Q, const __half* __restrict__ K,
    const __half* __restrict__ V, __half* __restrict__ O,
    const float* __restrict__ sW2, const float* __restrict__ sWo,
    __half* __restrict__ dW2, __half* __restrict__ dWo)
{
    extern __shared__ char smraw[];

    const int tid  = threadIdx.x;

    // ---- co-scheduled convert blocks (W2 then Wo) ----
    if (blockIdx.y >= FA_BH) {
        int blk = (blockIdx.y - FA_BH) * 16 + blockIdx.x;   // 0..1279
        int idx = blk * 256 + tid;
        if (idx < NFF16) {
            cvt16(sW2, dW2, idx);
        } else {
            cvt16(sWo, dWo, idx - NFF16);
        }
        return;
    }

    __half* Qs = (__half*)smraw;
    const int lane = tid & 31, w = tid >> 5;
    const int g = lane >> 2, t4 = lane & 3;
    const int lr = lane & 15;
    const int lc = (lane >> 4) << 3;

    const int qb = (int)gridDim.x - 1 - (int)blockIdx.x;
    const int bh = blockIdx.y;
    const int b = bh >> 4, h = bh & 15;

    const size_t base = ((size_t)b * SEQ) * DMODEL + h * DHEAD;
    const __half* Qg = Q + base + (size_t)(qb * 128) * DMODEL;
    const __half* Kg = K + base;
    const __half* Vg = V + base;

    #pragma unroll
    for (int e = 0; e < 4; ++e) {
        int id  = e * 256 + tid;
        int row = id >> 3;
        int c16 = id & 7;
        unsigned int sw = (unsigned int)(row * 128) + (((unsigned int)c16 ^ ((unsigned int)row & 7u)) * 16u);
        unsigned int sa = (unsigned int)__cvta_generic_to_shared(smraw + sw);
        asm volatile("cp.async.cg.shared.global [%0], [%1], 16;\n"
                     :: "r"(sa), "l"(Qg + (size_t)row * DMODEL + c16 * 8));
    }
    asm volatile("cp.async.commit_group;\n");

    auto load_kv = [&](int t, int buf) {
        const __half* Ksrc = Kg + (size_t)(t * 64) * DMODEL;
        const __half* Vsrc = Vg + (size_t)(t * 64) * DMODEL;
        char* Kdst = smraw + FA_Q_BYTES + buf * FA_KV_BYTES;
        char* Vdst = smraw + FA_Q_BYTES + 3 * FA_KV_BYTES + buf * FA_KV_BYTES;
        #pragma unroll
        for (int e = 0; e < 2; ++e) {
            int id  = e * 256 + tid;
            int row = id >> 3;
            int c16 = id & 7;
            unsigned int sw = (unsigned int)(row * 128) + (((unsigned int)c16 ^ ((unsigned int)row & 7u)) * 16u);
            unsigned int sk = (unsigned int)__cvta_generic_to_shared(Kdst + sw);
            asm volatile("cp.async.cg.shared.global [%0], [%1], 16;\n"
                         :: "r"(sk), "l"(Ksrc + (size_t)row * DMODEL + c16 * 8));
            unsigned int sv = (unsigned int)__cvta_generic_to_shared(Vdst + sw);
            asm volatile("cp.async.cg.shared.global [%0], [%1], 16;\n"
                         :: "r"(sv), "l"(Vsrc + (size_t)row * DMODEL + c16 * 8));
        }
        asm volatile("cp.async.commit_group;\n");
    };

    load_kv(0, 0);
    load_kv(1, 1);

    asm volatile("cp.async.wait_group 2;\n");
    __syncthreads();

    unsigned int aq[4][4];
    #pragma unroll
    for (int dt = 0; dt < 4; ++dt)
        ldsm4h(aq[dt], swp(Qs, 16 * w + lr, dt * 16 + lc));

    float o_acc[8][4];
    #pragma unroll
    for (int j = 0; j < 8; ++j)
        #pragma unroll
        for (int r = 0; r < 4; ++r) o_acc[j][r] = 0.0f;

    float m0 = -INFINITY, m1 = -INFINITY, l0 = 0.0f, l1 = 0.0f;

    const float CE = 0.125f * 1.44269504f;
    const unsigned int bones[2] = {0x3C003C00u, 0x3C003C00u};

    const int T = 2 * qb + 2;

    for (int t = 0; t < T; ++t) {
        if (t + 1 < T) asm volatile("cp.async.wait_group 1;\n");
        else           asm volatile("cp.async.wait_group 0;\n");
        __syncthreads();

        if (t + 2 < T) load_kv(t + 2, (t + 2) % 3);

        const bool skip = (16 * w + 15) < (64 * t - 128 * qb);
        if (!skip) {
            const __half* Ksb = (const __half*)(smraw + FA_Q_BYTES + (t % 3) * FA_KV_BYTES);
            const __half* Vsb = (const __half*)(smraw + FA_Q_BYTES + 3 * FA_KV_BYTES + (t % 3) * FA_KV_BYTES);

            float s[8][4];
            #pragma unroll
            for (int j = 0; j < 8; ++j)
                #pragma unroll
                for (int r = 0; r < 4; ++r) s[j][r] = 0.0f;

            const int sft = lane >> 3;
            #pragma unroll
            for (int dt = 0; dt < 4; ++dt) {
                #pragma unroll
                for (int jp = 0; jp < 4; ++jp) {
                    unsigned int bk[4];
                    ldsm4h(bk, swp(Ksb, 8 * (2 * jp + (sft >> 1)) + (lane & 7),
                                   dt * 16 + ((sft & 1) << 3)));
                    mma_f16(s[2 * jp],     aq[dt], bk);
                    mma_f16(s[2 * jp + 1], aq[dt], bk + 2);
                }
            }

            if (t >= 2 * qb) {
                const int q0r = 128 * qb + 16 * w + g;
                #pragma unroll
                for (int j = 0; j < 8; ++j) {
                    const int kk = 64 * t + 8 * j + 2 * t4;
                    if (kk     > q0r)     s[j][0] = -INFINITY;
                    if (kk + 1 > q0r)     s[j][1] = -INFINITY;
                    if (kk     > q0r + 8) s[j][2] = -INFINITY;
                    if (kk + 1 > q0r + 8) s[j][3] = -INFINITY;
                }
            }

            float mt0 = -INFINITY, mt1 = -INFINITY;
            #pragma unroll
            for (int j = 0; j < 8; ++j) {
                mt0 = fmaxf(mt0, fmaxf(s[j][0], s[j][1]));
                mt1 = fmaxf(mt1, fmaxf(s[j][2], s[j][3]));
            }
            mt0 = fmaxf(mt0, __shfl_xor_sync(0xffffffffu, mt0, 1));
            mt0 = fmaxf(mt0, __shfl_xor_sync(0xffffffffu, mt0, 2));
            mt1 = fmaxf(mt1, __shfl_xor_sync(0xffffffffu, mt1, 1));
            mt1 = fmaxf(mt1, __shfl_xor_sync(0xffffffffu, mt1, 2));

            const float mn0 = fmaxf(m0, mt0);
            const float mn1 = fmaxf(m1, mt1);
            const float sc0 = ex2f((m0 - mn0) * CE);
            const float sc1 = ex2f((m1 - mn1) * CE);
            const float bexp0 = mn0 * CE;
            const float bexp1 = mn1 * CE;

            unsigned int ap[4][4];
            #pragma unroll
            for (int j = 0; j < 8; ++j) {
                float d0 = fmaf(s[j][0], CE, -bexp0);
                float d1 = fmaf(s[j][1], CE, -bexp0);
                float d2 = fmaf(s[j][2], CE, -bexp1);
                float d3 = fmaf(s[j][3], CE, -bexp1);
                __half2 e01 = h2exp2(__floats2half2_rn(d0, d1));
                __half2 e23 = h2exp2(__floats2half2_rn(d2, d3));
                const int kt = j >> 1;
                if ((j & 1) == 0) {
                    ap[kt][0] = *(unsigned int*)&e01;
                    ap[kt][1] = *(unsigned int*)&e23;
                } else {
                    ap[kt][2] = *(unsigned int*)&e01;
                    ap[kt][3] = *(unsigned int*)&e23;
                }
            }

            float sm[4] = {0.0f, 0.0f, 0.0f, 0.0f};
            #pragma unroll
            for (int kt = 0; kt < 4; ++kt)
                mma_f16(sm, ap[kt], bones);

            l0 = l0 * sc0 + sm[0];
            l1 = l1 * sc1 + sm[2];
            m0 = mn0;
            m1 = mn1;

            #pragma unroll
            for (int j = 0; j < 8; ++j) {
                o_acc[j][0] *= sc0; o_acc[j][1] *= sc0;
                o_acc[j][2] *= sc1; o_acc[j][3] *= sc1;
            }

            #pragma unroll
            for (int kt = 0; kt < 4; ++kt) {
                #pragma unroll
                for (int jp = 0; jp < 4; ++jp) {
                    unsigned int bv[4];
                    ldsm4ht(bv, swp(Vsb, 16 * kt + ((sft & 1) << 3) + (lane & 7),
                                    16 * jp + ((sft >> 1) << 3)));
                    mma_f16(o_acc[2 * jp],     ap[kt], bv);
                    mma_f16(o_acc[2 * jp + 1], ap[kt], bv + 2);
                }
            }
        }
    }

    const float inv0 = 1.0f / l0;
    const float inv1 = 1.0f / l1;
    __half* Og = O + base + (size_t)(qb * 128 + 16 * w) * DMODEL;
    #pragma unroll
    for (int j = 0; j < 8; ++j) {
        const int d = 8 * j + 2 * t4;
        *(__half2*)(Og + (size_t)g * DMODEL + d) =
            __floats2half2_rn(o_acc[j][0] * inv0, o_acc[j][1] * inv0);
        *(__half2*)(Og + (size_t)(g + 8) * DMODEL + d) =
            __floats2half2_rn(o_acc[j][2] * inv1, o_acc[j][3] * inv1);
    }
}

// ---------------------------------------------------------------------------
// Launch
// ---------------------------------------------------------------------------
extern "C" void kernel_launch(void* const* d_in, const int* in_sizes, int n_in,
                              void* d_out, int out_size)
{
    const float* x  = (const float*)d_in[0];
    const float* Wq = (const float*)d_in[1];
    const float* Wk = (const float*)d_in[2];
    const float* Wv = (const float*)d_in[3];
    const float* Wo = (const float*)d_in[4];
    const float* W1 = (const float*)d_in[5];
    const float* W2 = (const float*)d_in[6];
    const float* W3 = (const float*)d_in[7];
    const float* g1 = (const float*)d_in[8];
    const float* g2 = (const float*)d_in[9];
    float* out = (float*)d_out;

    __half *h1, *q, *k, *v, *o, *a;
    __half *wq, *wk, *wv, *wo, *w1, *w2, *w3;
    float *x2;
    cudaGetSymbolAddress((void**)&h1, g_h1);
    cudaGetSymbolAddress((void**)&q,  g_q);
    cudaGetSymbolAddress((void**)&k,  g_k);
    cudaGetSymbolAddress((void**)&v,  g_v);
    cudaGetSymbolAddress((void**)&o,  g_o);
    cudaGetSymbolAddress((void**)&x2, g_x2);
    cudaGetSymbolAddress((void**)&a,  g_a);
    cudaGetSymbolAddress((void**)&wq, g_wq);
    cudaGetSymbolAddress((void**)&wk, g_wk);
    cudaGetSymbolAddress((void**)&wv, g_wv);
    cudaGetSymbolAddress((void**)&wo, g_wo);
    cudaGetSymbolAddress((void**)&w1, g_w1);
    cudaGetSymbolAddress((void**)&w2, g_w2);
    cudaGetSymbolAddress((void**)&w3, g_w3);

    cudaFuncSetAttribute(flash_attn_kernel,
                         cudaFuncAttributeMaxDynamicSharedMemorySize, FA_SMEM_BYTES);
    cudaFuncSetAttribute(gemm_f16<0>,
                         cudaFuncAttributeMaxDynamicSharedMemorySize, GF_SMEM);
    cudaFuncSetAttribute(gemm_f16<1>,
                         cudaFuncAttributeMaxDynamicSharedMemorySize, GF_SMEM);
    cudaFuncSetAttribute(gemm_swiglu,
                         cudaFuncAttributeMaxDynamicSharedMemorySize, GS_SMEM);

    const dim3 gemm_qkv(DMODEL / 128, NTOK / 128, 4);   // z==3: convert W1,W3
    const dim3 gemm_d_d(DMODEL / 128, NTOK / 128, 1);
    const dim3 gemm_sw(DFF / 64, NTOK / 128);

    // 0+1) fused: rmsnorm1 + convert Wq,Wk,Wv
    prelude_kernel<<<NTOK + NQKVCVT, 256>>>(x, g1, h1,
                                            Wq, Wk, Wv,
                                            wq, wk, wv);

    // 2) q,k,v GEMM + convert W1,W3 (z==3)
    gemm_f16<0><<<gemm_qkv, 256, GF_SMEM>>>(h1, wq, wk, wv, nullptr,
                                            q, k, v, NTOK, DMODEL, DMODEL,
                                            W1, W3, w1, w3);

    // 3) attention + convert W2,Wo
    dim3 fa_grid(SEQ / 128, FA_BH + FA_CVT_ROWS);
    flash_attn_kernel<<<fa_grid, 256, FA_SMEM_BYTES>>>(q, k, v, o,
                                                       W2, Wo, w2, wo);

    // 4) x2 = x + o @ Wo^T (fp32 out)
    gemm_f16<1><<<gemm_d_d, 256, GF_SMEM>>>(o, wo, wo, wo, x,
                                            x2, x2, x2, NTOK, DMODEL, DMODEL,
                                            nullptr, nullptr, nullptr, nullptr);

    // 5) h2 = rmsnorm(x2, g2) -> fp16
    rmsnorm_kernel<<<NTOK, 256>>>(x2, g2, h1);

    // 6) a = silu(h2 @ W1^T) * (h2 @ W3^T)
    gemm_swiglu<<<gemm_sw, 256, GS_SMEM>>>(h1, w1, w3, a, DMODEL);

    // 7) out = x2 + a @ W2^T (fp32 out)
    gemm_f16<1><<<gemm_d_d, 256, GF_SMEM>>>(a, w2, w2, w2, x2,
                                            out, out, out, NTOK, DMODEL, DFF,
                                            nullptr, nullptr, nullptr, nullptr);
}

// round 17
// speedup vs baseline: 1.0229x; 1.0214x over previous
#include <cuda_runtime.h>
#include <cuda_fp16.h>
#include <stdint.h>
#include <math.h>

// Problem constants
#define BATCH 2
#define SEQ 2048
#define DMODEL 1024
#define NHEADS 16
#define DHEAD 64
#define DFF 4096
#define NTOK (BATCH * SEQ)   // 4096

// ---------------------------------------------------------------------------
// Scratch (device globals; allocation is forbidden)
// ---------------------------------------------------------------------------
__device__ __half g_h1[NTOK * DMODEL];
__device__ __half g_q [NTOK * DMODEL];
__device__ __half g_k [NTOK * DMODEL];
__device__ __half g_v [NTOK * DMODEL];
__device__ __half g_o [NTOK * DMODEL];
__device__ float  g_x2[NTOK * DMODEL];
__device__ __half g_a [NTOK * DFF];
// fp16 weights
__device__ __half g_wq[DMODEL * DMODEL];
__device__ __half g_wk[DMODEL * DMODEL];
__device__ __half g_wv[DMODEL * DMODEL];
__device__ __half g_wo[DMODEL * DMODEL];
__device__ __half g_w1[DFF * DMODEL];
__device__ __half g_w2[DMODEL * DFF];
__device__ __half g_w3[DFF * DMODEL];

// ---------------------------------------------------------------------------
// mma.sync helpers
// ---------------------------------------------------------------------------
__device__ __forceinline__ void mma_f16(float* c, const unsigned int* a, const unsigned int* b) {
    asm volatile(
        "mma.sync.aligned.m16n8k16.row.col.f32.f16.f16.f32 "
        "{%0,%1,%2,%3}, {%4,%5,%6,%7}, {%8,%9}, {%0,%1,%2,%3};"
        : "+f"(c[0]), "+f"(c[1]), "+f"(c[2]), "+f"(c[3])
        : "r"(a[0]), "r"(a[1]), "r"(a[2]), "r"(a[3]), "r"(b[0]), "r"(b[1]));
}
__device__ __forceinline__ void ldsm4h(unsigned int* r, const __half* p) {
    unsigned int addr = (unsigned int)__cvta_generic_to_shared(p);
    asm volatile("ldmatrix.sync.aligned.m8n8.x4.shared.b16 {%0,%1,%2,%3}, [%4];"
                 : "=r"(r[0]), "=r"(r[1]), "=r"(r[2]), "=r"(r[3]) : "r"(addr));
}
__device__ __forceinline__ void ldsm4ht(unsigned int* r, const __half* p) {
    unsigned int addr = (unsigned int)__cvta_generic_to_shared(p);
    asm volatile("ldmatrix.sync.aligned.m8n8.x4.trans.shared.b16 {%0,%1,%2,%3}, [%4];"
                 : "=r"(r[0]), "=r"(r[1]), "=r"(r[2]), "=r"(r[3]) : "r"(addr));
}
__device__ __forceinline__ float ex2f(float x) {
    float y;
    asm("ex2.approx.ftz.f32 %0, %1;" : "=f"(y) : "f"(x));
    return y;
}

// SW128 swizzled pointer within a [rows x 128 bytes] tile. halfcol multiple of 8.
__device__ __forceinline__ const __half* swp(const __half* base, int row, int halfcol) {
    unsigned int off = (unsigned int)(row * 128) +
        (((unsigned int)(halfcol * 2)) ^ (((unsigned int)row & 7u) * 16u));
    return (const __half*)((const char*)base + off);
}

// convert helper: 16 floats -> 16 halfs at unit index `off`
__device__ __forceinline__ void cvt16(const float* __restrict__ src,
                                      __half* __restrict__ dst, int off) {
    float4 v0 = *(const float4*)(src + (size_t)off * 16);
    float4 v1 = *(const float4*)(src + (size_t)off * 16 + 4);
    float4 v2 = *(const float4*)(src + (size_t)off * 16 + 8);
    float4 v3 = *(const float4*)(src + (size_t)off * 16 + 12);
    __half2 h[8];
    h[0] = __floats2half2_rn(v0.x, v0.y);
    h[1] = __floats2half2_rn(v0.z, v0.w);
    h[2] = __floats2half2_rn(v1.x, v1.y);
    h[3] = __floats2half2_rn(v1.z, v1.w);
    h[4] = __floats2half2_rn(v2.x, v2.y);
    h[5] = __floats2half2_rn(v2.z, v2.w);
    h[6] = __floats2half2_rn(v3.x, v3.y);
    h[7] = __floats2half2_rn(v3.z, v3.w);
    *(uint4*)(dst + (size_t)off * 16)     = ((uint4*)h)[0];
    *(uint4*)(dst + (size_t)off * 16 + 8) = ((uint4*)h)[1];
}

// ---------------------------------------------------------------------------
// Prelude: rmsnorm1 + converts for Wq,Wk,Wv (the QKV critical path only).
// ---------------------------------------------------------------------------
#define NDD16 (DMODEL * DMODEL / 16)   // 65536
#define NFF16 (DFF * DMODEL / 16)      // 262144
#define NQKVCVT (3 * NDD16 / 256)      // 768 blocks

__global__ __launch_bounds__(256) void prelude_kernel(
    const float* __restrict__ x, const float* __restrict__ g1,
    __half* __restrict__ h1,
    const float* __restrict__ s0, const float* __restrict__ s1,
    const float* __restrict__ s2,
    __half* __restrict__ d0, __half* __restrict__ d1,
    __half* __restrict__ d2)
{
    const int tid = threadIdx.x;

    if (blockIdx.x < NTOK) {
        const int row = blockIdx.x;
        const float* xr = x + (size_t)row * DMODEL;

        float4 v = *(const float4*)(xr + tid * 4);
        float ss = v.x * v.x + v.y * v.y + v.z * v.z + v.w * v.w;

        #pragma unroll
        for (int off = 16; off; off >>= 1)
            ss += __shfl_xor_sync(0xffffffffu, ss, off);

        __shared__ float red[8];
        const int lane = tid & 31, warp = tid >> 5;
        if (lane == 0) red[warp] = ss;
        __syncthreads();
        if (warp == 0) {
            float t = (lane < 8) ? red[lane] : 0.0f;
            #pragma unroll
            for (int off = 4; off; off >>= 1)
                t += __shfl_xor_sync(0xffffffffu, t, off);
            if (lane == 0) red[0] = t;
        }
        __syncthreads();

        const float inv = rsqrtf(red[0] * (1.0f / DMODEL) + 1e-5f);
        float4 gv = *(const float4*)(g1 + tid * 4);
        __half2 h0 = __floats2half2_rn(v.x * inv * gv.x, v.y * inv * gv.y);
        __half2 hh = __floats2half2_rn(v.z * inv * gv.z, v.w * inv * gv.w);
        __half* yp = h1 + (size_t)row * DMODEL + tid * 4;
        *(__half2*)(yp)     = h0;
        *(__half2*)(yp + 2) = hh;
    } else {
        int idx = (blockIdx.x - NTOK) * 256 + tid;
        int seg = idx / NDD16;
        int off = idx - seg * NDD16;
        const float* src = (seg == 0) ? s0 : (seg == 1) ? s1 : s2;
        __half* dst      = (seg == 0) ? d0 : (seg == 1) ? d1 : d2;
        cvt16(src, dst, off);
    }
}

// ---------------------------------------------------------------------------
// RMSNorm (standalone, second norm): fp32 in -> fp16 out.
// ---------------------------------------------------------------------------
__global__ __launch_bounds__(256) void rmsnorm_kernel(
    const float* __restrict__ x, const float* __restrict__ g,
    __half* __restrict__ y)
{
    const int row = blockIdx.x;
    const int tid = threadIdx.x;
    const float* xr = x + (size_t)row * DMODEL;

    float4 v = *(const float4*)(xr + tid * 4);
    float ss = v.x * v.x + v.y * v.y + v.z * v.z + v.w * v.w;

    #pragma unroll
    for (int off = 16; off; off >>= 1)
        ss += __shfl_xor_sync(0xffffffffu, ss, off);

    __shared__ float red[8];
    const int lane = tid & 31, warp = tid >> 5;
    if (lane == 0) red[warp] = ss;
    __syncthreads();
    if (warp == 0) {
        float t = (lane < 8) ? red[lane] : 0.0f;
        #pragma unroll
        for (int off = 4; off; off >>= 1)
            t += __shfl_xor_sync(0xffffffffu, t, off);
        if (lane == 0) red[0] = t;
    }
    __syncthreads();

    const float inv = rsqrtf(red[0] * (1.0f / DMODEL) + 1e-5f);
    float4 gv = *(const float4*)(g + tid * 4);
    __half2 h0 = __floats2half2_rn(v.x * inv * gv.x, v.y * inv * gv.y);
    __half2 h1 = __floats2half2_rn(v.z * inv * gv.z, v.w * inv * gv.w);
    __half* yp = y + (size_t)row * DMODEL + tid * 4;
    *(__half2*)(yp)     = h0;
    *(__half2*)(yp + 2) = h1;
}

// ---------------------------------------------------------------------------
// FP16 tensor-core GEMM (R11 config) + optional z==3 convert slice (W1+W3).
// ---------------------------------------------------------------------------
#define GF_STAGE_H (128 * 64)
#define GF_SMEM (6 * GF_STAGE_H * 2)     // 98304 bytes

template <int MODE>
__global__ __launch_bounds__(256, 2) void gemm_f16(
    const __half* __restrict__ A,
    const __half* __restrict__ B0, const __half* __restrict__ B1, const __half* __restrict__ B2,
    const float* __restrict__ R,
    void* __restrict__ C0v, void* __restrict__ C1v, void* __restrict__ C2v,
    int M, int N, int K,
    const float* __restrict__ S4, const float* __restrict__ S5,
    __half* __restrict__ D4, __half* __restrict__ D5)
{
    extern __shared__ __half smh[];
    __half* As = smh;
    __half* Bs = smh + 3 * GF_STAGE_H;

    const int z = blockIdx.z;
    const int tid  = threadIdx.x;

    if (MODE == 0 && z == 3) {
        int blk = blockIdx.y * (int)gridDim.x + blockIdx.x;   // 0..255
        #pragma unroll
        for (int u = 0; u < 8; ++u) {
            int idx = (blk * 8 + u) * 256 + tid;
            int seg = idx / NFF16;
            int off = idx - seg * NFF16;
            const float* src = (seg == 0) ? S4 : S5;
            __half* dst      = (seg == 0) ? D4 : D5;
            cvt16(src, dst, off);
        }
        return;
    }

    const __half* B = (z == 0) ? B0 : (z == 1) ? B1 : B2;
    void*         Cv = (z == 0) ? C0v : (z == 1) ? C1v : C2v;

    const int lane = tid & 31, warp = tid >> 5;
    const int g = lane >> 2, t4 = lane & 3;
    const int wm = warp >> 2, wn = warp & 3;
    const int bm = blockIdx.y, bn = blockIdx.x;

    const int lr = lane & 15;
    const int lc = (lane >> 4) << 3;
    const int sft = lane >> 3;

    const __half* Ab = A + (size_t)bm * 128 * K;
    const __half* Bb = B + (size_t)bn * 128 * K;

    float acc[4][4][4];
    #pragma unroll
    for (int i = 0; i < 4; ++i)
        #pragma unroll
        for (int j = 0; j < 4; ++j)
            #pragma unroll
            for (int r = 0; r < 4; ++r) acc[i][j][r] = 0.0f;

    const int T = K >> 6;

    auto load_tile = [&](int kt, int st) {
        const __half* Asrc = Ab + kt * 64;
        const __half* Bsrc = Bb + kt * 64;
        __half* Adst = As + st * GF_STAGE_H;
        __half* Bdst = Bs + st * GF_STAGE_H;
        #pragma unroll
        for (int e = 0; e < 4; ++e) {
            int id  = e * 256 + tid;
            int row = id >> 3;
            int c16 = id & 7;
            unsigned int sw = (unsigned int)(row * 128) + (((unsigned int)c16 ^ ((unsigned int)row & 7u)) * 16u);
            unsigned int sa = (unsigned int)__cvta_generic_to_shared((const char*)Adst + sw);
            asm volatile("cp.async.cg.shared.global [%0], [%1], 16;\n"
                         :: "r"(sa), "l"(Asrc + (size_t)row * K + c16 * 8));
            unsigned int sb = (unsigned int)__cvta_generic_to_shared((const char*)Bdst + sw);
            asm volatile("cp.async.cg.shared.global [%0], [%1], 16;\n"
                         :: "r"(sb), "l"(Bsrc + (size_t)row * K + c16 * 8));
        }
        asm volatile("cp.async.commit_group;\n");
    };

    load_tile(0, 0);
    load_tile(1, 1);

    for (int kt = 0; kt < T; ++kt) {
        if (kt + 1 < T) asm volatile("cp.async.wait_group 1;\n");
        else            asm volatile("cp.async.wait_group 0;\n");
        __syncthreads();

        if (kt + 2 < T) load_tile(kt + 2, (kt + 2) % 3);

        const __half* Asb = As + (kt % 3) * GF_STAGE_H;
        const __half* Bsb = Bs + (kt % 3) * GF_STAGE_H;

        #pragma unroll
        for (int ks = 0; ks < 4; ++ks) {
            const int k0 = ks * 16;
            unsigned int af[4][4], bf[2][4];
            #pragma unroll
            for (int i = 0; i < 4; ++i)
                ldsm4h(af[i], swp(Asb, wm * 64 + i * 16 + lr, k0 + lc));
            #pragma unroll
            for (int jp = 0; jp < 2; ++jp)
                ldsm4h(bf[jp], swp(Bsb, wn * 32 + 8 * (2 * jp + (sft >> 1)) + (lane & 7),
                                   k0 + ((sft & 1) << 3)));
            #pragma unroll
            for (int i = 0; i < 4; ++i)
                #pragma unroll
                for (int jp = 0; jp < 2; ++jp) {
                    mma_f16(acc[i][2 * jp],     af[i], bf[jp]);
                    mma_f16(acc[i][2 * jp + 1], af[i], bf[jp] + 2);
                }
        }
    }

    #pragma unroll
    for (int i = 0; i < 4; ++i) {
        const int r0 = bm * 128 + wm * 64 + i * 16 + g;
        #pragma unroll
        for (int j = 0; j < 4; ++j) {
            const int c0 = bn * 128 + wn * 32 + j * 8 + 2 * t4;
            if (MODE == 1) {
                float* C = (float*)Cv;
                float2 rr0 = *(const float2*)(R + (size_t)r0 * N + c0);
                float2 rr1 = *(const float2*)(R + (size_t)(r0 + 8) * N + c0);
                *(float2*)(C + (size_t)r0 * N + c0) =
                    make_float2(acc[i][j][0] + rr0.x, acc[i][j][1] + rr0.y);
                *(float2*)(C + (size_t)(r0 + 8) * N + c0) =
                    make_float2(acc[i][j][2] + rr1.x, acc[i][j][3] + rr1.y);
            } else {
                __half* C = (__half*)Cv;
                *(__half2*)(C + (size_t)r0 * N + c0) =
                    __floats2half2_rn(acc[i][j][0], acc[i][j][1]);
                *(__half2*)(C + (size_t)(r0 + 8) * N + c0) =
                    __floats2half2_rn(acc[i][j][2], acc[i][j][3]);
            }
        }
    }
}

// ---------------------------------------------------------------------------
// Fused W1/W3/SwiGLU GEMM (unchanged).
// ---------------------------------------------------------------------------
#define GS_A_H (128 * 64)
#define GS_B_H (64 * 64)
#define GS_SMEM ((3 * GS_A_H + 6 * GS_B_H) * 2)   // 98304 bytes

__global__ __launch_bounds__(256, 2) void gemm_swiglu(
    const __half* __restrict__ A,
    const __half* __restrict__ W1p, const __half* __restrict__ W3p,
    __half* __restrict__ Out, int K)
{
    extern __shared__ __half smh[];
    __half* As  = smh;
    __half* B1s = smh + 3 * GS_A_H;
    __half* B3s = B1s + 3 * GS_B_H;

    const int tid  = threadIdx.x;
    const int lane = tid & 31, warp = tid >> 5;
    const int g = lane >> 2, t4 = lane & 3;
    const int wm = warp >> 1, wn = warp & 1;
    const int bm = blockIdx.y, bn = blockIdx.x;

    const int lr = lane & 15;
    const int lc = (lane >> 4) << 3;
    const int sft = lane >> 3;

    const __half* Ab  = A   + (size_t)bm * 128 * K;
    const __half* B1b = W1p + (size_t)bn * 64 * K;
    const __half* B3b = W3p + (size_t)bn * 64 * K;

    float acc1[2][4][4], acc3[2][4][4];
    #pragma unroll
    for (int i = 0; i < 2; ++i)
        #pragma unroll
        for (int j = 0; j < 4; ++j)
            #pragma unroll
            for (int r = 0; r < 4; ++r) { acc1[i][j][r] = 0.0f; acc3[i][j][r] = 0.0f; }

    const int T = K >> 6;

    auto load_tile = [&](int kt, int st) {
        const __half* Asrc  = Ab  + kt * 64;
        const __half* B1src = B1b + kt * 64;
        const __half* B3src = B3b + kt * 64;
        __half* Adst  = As  + st * GS_A_H;
        __half* B1dst = B1s + st * GS_B_H;
        __half* B3dst = B3s + st * GS_B_H;
        #pragma unroll
        for (int e = 0; e < 4; ++e) {
            int id  = e * 256 + tid;
            int row = id >> 3;
            int c16 = id & 7;
            unsigned int sw = (unsigned int)(row * 128) + (((unsigned int)c16 ^ ((unsigned int)row & 7u)) * 16u);
            unsigned int sa = (unsigned int)__cvta_generic_to_shared((const char*)Adst + sw);
            asm volatile("cp.async.cg.shared.global [%0], [%1], 16;\n"
                         :: "r"(sa), "l"(Asrc + (size_t)row * K + c16 * 8));
        }
        #pragma unroll
        for (int e = 0; e < 2; ++e) {
            int id  = e * 256 + tid;
            int row = id >> 3;
            int c16 = id & 7;
            unsigned int sw = (unsigned int)(row * 128) + (((unsigned int)c16 ^ ((unsigned int)row & 7u)) * 16u);
            unsigned int s1 = (unsigned int)__cvta_generic_to_shared((const char*)B1dst + sw);
            asm volatile("cp.async.cg.shared.global [%0], [%1], 16;\n"
                         :: "r"(s1), "l"(B1src + (size_t)row * K + c16 * 8));
            unsigned int s3 = (unsigned int)__cvta_generic_to_shared((const char*)B3dst + sw);
            asm volatile("cp.async.cg.shared.global [%0], [%1], 16;\n"
                         :: "r"(s3), "l"(B3src + (size_t)row * K + c16 * 8));
        }
        asm volatile("cp.async.commit_group;\n");
    };

    load_tile(0, 0);
    load_tile(1, 1);

    for (int kt = 0; kt < T; ++kt) {
        if (kt + 1 < T) asm volatile("cp.async.wait_group 1;\n");
        else            asm volatile("cp.async.wait_group 0;\n");
        __syncthreads();

        if (kt + 2 < T) load_tile(kt + 2, (kt + 2) % 3);

        const __half* Asb  = As  + (kt % 3) * GS_A_H;
        const __half* B1sb = B1s + (kt % 3) * GS_B_H;
        const __half* B3sb = B3s + (kt % 3) * GS_B_H;

        #pragma unroll
        for (int ks = 0; ks < 4; ++ks) {
            const int k0 = ks * 16;
            unsigned int af[2][4], b1f[2][4], b3f[2][4];
            #pragma unroll
            for (int i = 0; i < 2; ++i)
                ldsm4h(af[i], swp(Asb, wm * 32 + i * 16 + lr, k0 + lc));
            #pragma unroll
            for (int jp = 0; jp < 2; ++jp) {
                const int brow = wn * 32 + 8 * (2 * jp + (sft >> 1)) + (lane & 7);
                const int bcol = k0 + ((sft & 1) << 3);
                ldsm4h(b1f[jp], swp(B1sb, brow, bcol));
                ldsm4h(b3f[jp], swp(B3sb, brow, bcol));
            }
            #pragma unroll
            for (int i = 0; i < 2; ++i)
                #pragma unroll
                for (int jp = 0; jp < 2; ++jp) {
                    mma_f16(acc1[i][2 * jp],     af[i], b1f[jp]);
                    mma_f16(acc1[i][2 * jp + 1], af[i], b1f[jp] + 2);
                    mma_f16(acc3[i][2 * jp],     af[i], b3f[jp]);
                    mma_f16(acc3[i][2 * jp + 1], af[i], b3f[jp] + 2);
                }
        }
    }

    #pragma unroll
    for (int i = 0; i < 2; ++i) {
        const int r0 = bm * 128 + wm * 32 + i * 16 + g;
        #pragma unroll
        for (int j = 0; j < 4; ++j) {
            const int c0 = bn * 64 + wn * 32 + j * 8 + 2 * t4;
            float o0 = acc1[i][j][0] * (1.0f / (1.0f + __expf(-acc1[i][j][0]))) * acc3[i][j][0];
            float o1 = acc1[i][j][1] * (1.0f / (1.0f + __expf(-acc1[i][j][1]))) * acc3[i][j][1];
            float o2 = acc1[i][j][2] * (1.0f / (1.0f + __expf(-acc1[i][j][2]))) * acc3[i][j][2];
            float o3 = acc1[i][j][3] * (1.0f / (1.0f + __expf(-acc1[i][j][3]))) * acc3[i][j][3];
            *(__half2*)(Out + (size_t)r0 * DFF + c0)       = __floats2half2_rn(o0, o1);
            *(__half2*)(Out + (size_t)(r0 + 8) * DFF + c0) = __floats2half2_rn(o2, o3);
        }
    }
}

// ---------------------------------------------------------------------------
// Flash attention, pairwise-balanced: grid (8, 32 + 160). CTA bx processes
// qb = 8+bx then qb = 7-bx (constant 34 k-tile units per CTA).
// y>=32: convert W2, Wo.
// ---------------------------------------------------------------------------
#define FA_Q_BYTES (128 * 128)
#define FA_KV_BYTES (64 * 128)
#define FA_SMEM_BYTES (FA_Q_BYTES + 6 * FA_KV_BYTES)   // 65536
#define FA_BH (BATCH * NHEADS)                          // 32
// W2 + Wo = NFF16 + NDD16 units = 1280 blocks = 160 rows of 8
#define FA_CVT_ROWS 160

__global__ __launch_bounds__(256) void flash_attn_kernel(
    const __half* __restrict__ Q, const __half* __restrict__ K,
    const __half* __restrict__ V, __half* __restrict__ O,
    const float* __restrict__ sW2, const float* __restrict__ sWo,
    __half* __restrict__ dW2, __half* __restrict__ dWo)
{
    extern __shared__ char smraw[];

    const int tid  = threadIdx.x;

    // ---- co-scheduled convert blocks (W2 then Wo) ----
    if (blockIdx.y >= FA_BH) {
        int blk = (blockIdx.y - FA_BH) * 8 + blockIdx.x;   // 0..1279
        int idx = blk * 256 + tid;
        if (idx < NFF16) {
            cvt16(sW2, dW2, idx);
        } else {
            cvt16(sWo, dWo, idx - NFF16);
        }
        return;
    }

    __half* Qs = (__half*)smraw;
    const int lane = tid & 31, w = tid >> 5;
    const int g = lane >> 2, t4 = lane & 3;
    const int lr = lane & 15;
    const int lc = (lane >> 4) << 3;
    const int sft = lane >> 3;

    const int bx = blockIdx.x;   // 0..7
    const int bh = blockIdx.y;
    const int b = bh >> 4, h = bh & 15;

    const size_t base = ((size_t)b * SEQ) * DMODEL + h * DHEAD;
    const __half* Kg = K + base;
    const __half* Vg = V + base;

    const float CE = 0.125f * 1.44269504f;
    const unsigned int bones[2] = {0x3C003C00u, 0x3C003C00u};

    auto load_kv = [&](int t, int buf) {
        const __half* Ksrc = Kg + (size_t)(t * 64) * DMODEL;
        const __half* Vsrc = Vg + (size_t)(t * 64) * DMODEL;
        char* Kdst = smraw + FA_Q_BYTES + buf * FA_KV_BYTES;
        char* Vdst = smraw + FA_Q_BYTES + 3 * FA_KV_BYTES + buf * FA_KV_BYTES;
        #pragma unroll
        for (int e = 0; e < 2; ++e) {
            int id  = e * 256 + tid;
            int row = id >> 3;
            int c16 = id & 7;
            unsigned int sw = (unsigned int)(row * 128) + (((unsigned int)c16 ^ ((unsigned int)row & 7u)) * 16u);
            unsigned int sk = (unsigned int)__cvta_generic_to_shared(Kdst + sw);
            asm volatile("cp.async.cg.shared.global [%0], [%1], 16;\n"
                         :: "r"(sk), "l"(Ksrc + (size_t)row * DMODEL + c16 * 8));
            unsigned int sv = (unsigned int)__cvta_generic_to_shared(Vdst + sw);
            asm volatile("cp.async.cg.shared.global [%0], [%1], 16;\n"
                         :: "r"(sv), "l"(Vsrc + (size_t)row * DMODEL + c16 * 8));
        }
        asm volatile("cp.async.commit_group;\n");
    };

    #pragma unroll 1
    for (int hf = 0; hf < 2; ++hf) {
        const int qb = (hf == 0) ? (8 + bx) : (7 - bx);

        if (hf == 1) __syncthreads();   // protect reused Q smem buffer

        const __half* Qg = Q + base + (size_t)(qb * 128) * DMODEL;

        // ---- load Q tile ----
        #pragma unroll
        for (int e = 0; e < 4; ++e) {
            int id  = e * 256 + tid;
            int row = id >> 3;
            int c16 = id & 7;
            unsigned int sw = (unsigned int)(row * 128) + (((unsigned int)c16 ^ ((unsigned int)row & 7u)) * 16u);
            unsigned int sa = (unsigned int)__cvta_generic_to_shared(smraw + sw);
            asm volatile("cp.async.cg.shared.global [%0], [%1], 16;\n"
                         :: "r"(sa), "l"(Qg + (size_t)row * DMODEL + c16 * 8));
        }
        asm volatile("cp.async.commit_group;\n");

        load_kv(0, 0);
        load_kv(1, 1);

        asm volatile("cp.async.wait_group 2;\n");
        __syncthreads();

        unsigned int aq[4][4];
        #pragma unroll
        for (int dt = 0; dt < 4; ++dt)
            ldsm4h(aq[dt], swp(Qs, 16 * w + lr, dt * 16 + lc));

        float o_acc[8][4];
        #pragma unroll
        for (int j = 0; j < 8; ++j)
            #pragma unroll
            for (int r = 0; r < 4; ++r) o_acc[j][r] = 0.0f;

        float m0 = -INFINITY, m1 = -INFINITY, l0 = 0.0f, l1 = 0.0f;

        const int T = 2 * qb + 2;

        for (int t = 0; t < T; ++t) {
            if (t + 1 < T) asm volatile("cp.async.wait_group 1;\n");
            else           asm volatile("cp.async.wait_group 0;\n");
            __syncthreads();

            if (t + 2 < T) load_kv(t + 2, (t + 2) % 3);

            const bool skip = (16 * w + 15) < (64 * t - 128 * qb);
            if (!skip) {
                const __half* Ksb = (const __half*)(smraw + FA_Q_BYTES + (t % 3) * FA_KV_BYTES);
                const __half* Vsb = (const __half*)(smraw + FA_Q_BYTES + 3 * FA_KV_BYTES + (t % 3) * FA_KV_BYTES);

                float s[8][4];
                #pragma unroll
                for (int j = 0; j < 8; ++j)
                    #pragma unroll
                    for (int r = 0; r < 4; ++r) s[j][r] = 0.0f;

                #pragma unroll
                for (int dt = 0; dt < 4; ++dt) {
                    #pragma unroll
                    for (int jp = 0; jp < 4; ++jp) {
                        unsigned int bk[4];
                        ldsm4h(bk, swp(Ksb, 8 * (2 * jp + (sft >> 1)) + (lane & 7),
                                       dt * 16 + ((sft & 1) << 3)));
                        mma_f16(s[2 * jp],     aq[dt], bk);
                        mma_f16(s[2 * jp + 1], aq[dt], bk + 2);
                    }
                }

                if (t >= 2 * qb) {
                    const int q0r = 128 * qb + 16 * w + g;
                    #pragma unroll
                    for (int j = 0; j < 8; ++j) {
                        const int kk = 64 * t + 8 * j + 2 * t4;
                        if (kk     > q0r)     s[j][0] = -INFINITY;
                        if (kk + 1 > q0r)     s[j][1] = -INFINITY;
                        if (kk     > q0r + 8) s[j][2] = -INFINITY;
                        if (kk + 1 > q0r + 8) s[j][3] = -INFINITY;
                    }
                }

                float mt0 = -INFINITY, mt1 = -INFINITY;
                #pragma unroll
                for (int j = 0; j < 8; ++j) {
                    mt0 = fmaxf(mt0, fmaxf(s[j][0], s[j][1]));
                    mt1 = fmaxf(mt1, fmaxf(s[j][2], s[j][3]));
                }
                mt0 = fmaxf(mt0, __shfl_xor_sync(0xffffffffu, mt0, 1));
                mt0 = fmaxf(mt0, __shfl_xor_sync(0xffffffffu, mt0, 2));
                mt1 = fmaxf(mt1, __shfl_xor_sync(0xffffffffu, mt1, 1));
                mt1 = fmaxf(mt1, __shfl_xor_sync(0xffffffffu, mt1, 2));

                const float mn0 = fmaxf(m0, mt0);
                const float mn1 = fmaxf(m1, mt1);
                const float sc0 = ex2f((m0 - mn0) * CE);
                const float sc1 = ex2f((m1 - mn1) * CE);
                const float bexp0 = mn0 * CE;
                const float bexp1 = mn1 * CE;

                unsigned int ap[4][4];
                #pragma unroll
                for (int j = 0; j < 8; ++j) {
                    float d0 = fmaf(s[j][0], CE, -bexp0);
                    float d1 = fmaf(s[j][1], CE, -bexp0);
                    float d2 = fmaf(s[j][2], CE, -bexp1);
                    float d3 = fmaf(s[j][3], CE, -bexp1);
                    __half2 e01 = h2exp2(__floats2half2_rn(d0, d1));
                    __half2 e23 = h2exp2(__floats2half2_rn(d2, d3));
                    const int kt = j >> 1;
                    if ((j & 1) == 0) {
                        ap[kt][0] = *(unsigned int*)&e01;
                        ap[kt][1] = *(unsigned int*)&e23;
                    } else {
                        ap[kt][2] = *(unsigned int*)&e01;
                        ap[kt][3] = *(unsigned int*)&e23;
                    }
                }

                float sm[4] = {0.0f, 0.0f, 0.0f, 0.0f};
                #pragma unroll
                for (int kt = 0; kt < 4; ++kt)
                    mma_f16(sm, ap[kt], bones);

                l0 = l0 * sc0 + sm[0];
                l1 = l1 * sc1 + sm[2];
                m0 = mn0;
                m1 = mn1;

                #pragma unroll
                for (int j = 0; j < 8; ++j) {
                    o_acc[j][0] *= sc0; o_acc[j][1] *= sc0;
                    o_acc[j][2] *= sc1; o_acc[j][3] *= sc1;
                }

                #pragma unroll
                for (int kt = 0; kt < 4; ++kt) {
                    #pragma unroll
                    for (int jp = 0; jp < 4; ++jp) {
                        unsigned int bv[4];
                        ldsm4ht(bv, swp(Vsb, 16 * kt + ((sft & 1) << 3) + (lane & 7),
                                        16 * jp + ((sft >> 1) << 3)));
                        mma_f16(o_acc[2 * jp],     ap[kt], bv);
                        mma_f16(o_acc[2 * jp + 1], ap[kt], bv + 2);
                    }
                }
            }
        }

        const float inv0 = 1.0f / l0;
        const float inv1 = 1.0f / l1;
        __half* Og = O + base + (size_t)(qb * 128 + 16 * w) * DMODEL;
        #pragma unroll
        for (int j = 0; j < 8; ++j) {
            const int d = 8 * j + 2 * t4;
            *(__half2*)(Og + (size_t)g * DMODEL + d) =
                __floats2half2_rn(o_acc[j][0] * inv0, o_acc[j][1] * inv0);
            *(__half2*)(Og + (size_t)(g + 8) * DMODEL + d) =
                __floats2half2_rn(o_acc[j][2] * inv1, o_acc[j][3] * inv1);
        }
    }
}

// ---------------------------------------------------------------------------
// Launch
// ---------------------------------------------------------------------------
extern "C" void kernel_launch(void* const* d_in, const int* in_sizes, int n_in,
                              void* d_out, int out_size)
{
    const float* x  = (const float*)d_in[0];
    const float* Wq = (const float*)d_in[1];
    const float* Wk = (const float*)d_in[2];
    const float* Wv = (const float*)d_in[3];
    const float* Wo = (const float*)d_in[4];
    const float* W1 = (const float*)d_in[5];
    const float* W2 = (const float*)d_in[6];
    const float* W3 = (const float*)d_in[7];
    const float* g1 = (const float*)d_in[8];
    const float* g2 = (const float*)d_in[9];
    float* out = (float*)d_out;

    __half *h1, *q, *k, *v, *o, *a;
    __half *wq, *wk, *wv, *wo, *w1, *w2, *w3;
    float *x2;
    cudaGetSymbolAddress((void**)&h1, g_h1);
    cudaGetSymbolAddress((void**)&q,  g_q);
    cudaGetSymbolAddress((void**)&k,  g_k);
    cudaGetSymbolAddress((void**)&v,  g_v);
    cudaGetSymbolAddress((void**)&o,  g_o);
    cudaGetSymbolAddress((void**)&x2, g_x2);
    cudaGetSymbolAddress((void**)&a,  g_a);
    cudaGetSymbolAddress((void**)&wq, g_wq);
    cudaGetSymbolAddress((void**)&wk, g_wk);
    cudaGetSymbolAddress((void**)&wv, g_wv);
    cudaGetSymbolAddress((void**)&wo, g_wo);
    cudaGetSymbolAddress((void**)&w1, g_w1);
    cudaGetSymbolAddress((void**)&w2, g_w2);
    cudaGetSymbolAddress((void**)&w3, g_w3);

    cudaFuncSetAttribute(flash_attn_kernel,
                         cudaFuncAttributeMaxDynamicSharedMemorySize, FA_SMEM_BYTES);
    cudaFuncSetAttribute(gemm_f16<0>,
                         cudaFuncAttributeMaxDynamicSharedMemorySize, GF_SMEM);
    cudaFuncSetAttribute(gemm_f16<1>,
                         cudaFuncAttributeMaxDynamicSharedMemorySize, GF_SMEM);
    cudaFuncSetAttribute(gemm_swiglu,
                         cudaFuncAttributeMaxDynamicSharedMemorySize, GS_SMEM);

    const dim3 gemm_qkv(DMODEL / 128, NTOK / 128, 4);   // z==3: convert W1,W3
    const dim3 gemm_d_d(DMODEL / 128, NTOK / 128, 1);
    const dim3 gemm_sw(DFF / 64, NTOK / 128);

    // 0+1) fused: rmsnorm1 + convert Wq,Wk,Wv
    prelude_kernel<<<NTOK + NQKVCVT, 256>>>(x, g1, h1,
                                            Wq, Wk, Wv,
                                            wq, wk, wv);

    // 2) q,k,v GEMM + convert W1,W3 (z==3)
    gemm_f16<0><<<gemm_qkv, 256, GF_SMEM>>>(h1, wq, wk, wv, nullptr,
                                            q, k, v, NTOK, DMODEL, DMODEL,
                                            W1, W3, w1, w3);

    // 3) attention (pairwise-balanced) + convert W2,Wo
    dim3 fa_grid(SEQ / 256, FA_BH + FA_CVT_ROWS);
    flash_attn_kernel<<<fa_grid, 256, FA_SMEM_BYTES>>>(q, k, v, o,
                                                       W2, Wo, w2, wo);

    // 4) x2 = x + o @ Wo^T (fp32 out)
    gemm_f16<1><<<gemm_d_d, 256, GF_SMEM>>>(o, wo, wo, wo, x,
                                            x2, x2, x2, NTOK, DMODEL, DMODEL,
                                            nullptr, nullptr, nullptr, nullptr);

    // 5) h2 = rmsnorm(x2, g2) -> fp16
    rmsnorm_kernel<<<NTOK, 256>>>(x2, g2, h1);

    // 6) a = silu(h2 @ W1^T) * (h2 @ W3^T)
    gemm_swiglu<<<gemm_sw, 256, GS_SMEM>>>(h1, w1, w3, a, DMODEL);

    // 7) out = x2 + a @ W2^T (fp32 out)
    gemm_f16<1><<<gemm_d_d, 256, GF_SMEM>>>(a, w2, w2, w2, x2,
                                            out, out, out, NTOK, DMODEL, DFF,
                                            nullptr, nullptr, nullptr, nullptr);
}